// round 2
// baseline (speedup 1.0000x reference)
#include <cuda_runtime.h>
#include <cuda_bf16.h>
#include <cstdint>
#include <cstddef>

// Problem dims (fixed by dataset)
#define BB 32
#define SS 1024
#define II 512
#define HH 512
#define NB 128        // persistent blocks in recurrence
#define NT 128        // threads per recurrence block

// ---------------------------------------------------------------------------
// Scratch (device globals: allocation-free per harness rules)
// G layout: [s][n][b], n = gate*512 + hcol, gate order z,i,f,o.  256 MB.
__device__ float g_G[(size_t)SS * 2048 * BB];
// Hist layout: [s'][b][h] for s' = s-512.  32 MB.
__device__ float g_Hist[(size_t)(SS / 2) * BB * HH];
// Ping-pong hidden state, layout [buf][b][h].
__device__ float g_hbuf[2][BB * HH];
// Generation grid barrier (replay-safe: g_cnt returns to 0, g_gen is monotone)
__device__ unsigned g_cnt;
__device__ volatile unsigned g_gen;

__device__ __forceinline__ float sigf(float x) { return 1.0f / (1.0f + expf(-x)); }

// ---------------------------------------------------------------------------
// Input projection GEMM: G[s][n][b] = sum_i x[b][s][i] * W_g[h][i] + b_g[h]
// M = 32768 (m = s*32+b), N = 2048, K = 512.  Tiles 128x128x8, 8x8 micro.
__global__ void __launch_bounds__(256) input_gemm(
    const float* __restrict__ x,
    const float* __restrict__ Wz, const float* __restrict__ Wi,
    const float* __restrict__ Wf, const float* __restrict__ Wo,
    const float* __restrict__ bz, const float* __restrict__ bi,
    const float* __restrict__ bf, const float* __restrict__ bo)
{
    constexpr int BM = 128, BN = 128, BK = 8, TM = 8, TN = 8;
    __shared__ float As[BK][BM + 4];
    __shared__ float Bs[BK][BN + 4];

    const int bx = blockIdx.x;            // n-tile: 0..15
    const int by = blockIdx.y;            // m-tile: 0..255
    const int gate = bx >> 2;
    const float* W    = (gate == 0) ? Wz : (gate == 1) ? Wi : (gate == 2) ? Wf : Wo;
    const float* bias = (gate == 0) ? bz : (gate == 1) ? bi : (gate == 2) ? bf : bo;
    const int nloc0 = (bx & 3) * BN;      // row offset within this gate's W
    const int m0 = by * BM;

    const int tid  = threadIdx.x;
    const int arow = tid >> 1, acol = (tid & 1) * 4;   // A tile loader
    const int brow = tid >> 1, bcol = (tid & 1) * 4;   // B tile loader
    const int tx = tid & 15, ty = tid >> 4;
    const int tm0 = ty * TM, tn0 = tx * TN;

    const int am = m0 + arow;
    const float* aptr = x + (size_t)(am & 31) * (SS * II) + (size_t)(am >> 5) * II;
    const float* bptr = W + (size_t)(nloc0 + brow) * II;

    float acc[TM][TN];
#pragma unroll
    for (int i = 0; i < TM; i++)
#pragma unroll
        for (int j = 0; j < TN; j++) acc[i][j] = 0.0f;

    for (int k0 = 0; k0 < II; k0 += BK) {
        float4 av = *(const float4*)(aptr + k0 + acol);
        float4 bv = *(const float4*)(bptr + k0 + bcol);
        As[acol + 0][arow] = av.x; As[acol + 1][arow] = av.y;
        As[acol + 2][arow] = av.z; As[acol + 3][arow] = av.w;
        Bs[bcol + 0][brow] = bv.x; Bs[bcol + 1][brow] = bv.y;
        Bs[bcol + 2][brow] = bv.z; Bs[bcol + 3][brow] = bv.w;
        __syncthreads();
#pragma unroll
        for (int k = 0; k < BK; k++) {
            float ra[TM], rb[TN];
            *(float4*)(ra)     = *(const float4*)(&As[k][tm0]);
            *(float4*)(ra + 4) = *(const float4*)(&As[k][tm0 + 4]);
            *(float4*)(rb)     = *(const float4*)(&Bs[k][tn0]);
            *(float4*)(rb + 4) = *(const float4*)(&Bs[k][tn0 + 4]);
#pragma unroll
            for (int i = 0; i < TM; i++)
#pragma unroll
                for (int j = 0; j < TN; j++)
                    acc[i][j] = fmaf(ra[i], rb[j], acc[i][j]);
        }
        __syncthreads();
    }

    // Epilogue: 8 consecutive m within one s (tile aligned), so b consecutive.
    const int sB = (m0 + tm0) >> 5;
    const int bB = (m0 + tm0) & 31;
#pragma unroll
    for (int j = 0; j < TN; j++) {
        const int n = bx * BN + tn0 + j;
        const float bv = bias[nloc0 + tn0 + j];
        float* dst = g_G + ((size_t)sB * 2048 + n) * BB + bB;
        float4 v0 = make_float4(acc[0][j] + bv, acc[1][j] + bv, acc[2][j] + bv, acc[3][j] + bv);
        float4 v1 = make_float4(acc[4][j] + bv, acc[5][j] + bv, acc[6][j] + bv, acc[7][j] + bv);
        *(float4*)(dst)     = v0;
        *(float4*)(dst + 4) = v1;
    }
}

// ---------------------------------------------------------------------------
// Persistent recurrence kernel. 128 blocks x 128 threads, 1 block/SM.
// Block j owns H-columns [4j, 4j+4) for all 4 gates (16 rows of R in smem).
// h state is ping-pong double-buffered in g_hbuf: step s reads buf[(s-1)&1],
// writes buf[s&1]; one generation grid-barrier per step gives both release
// (writes visible) and WAR safety (buffer overwritten only 2 steps later,
// after its readers provably arrived at an interleaving barrier).
__global__ void __launch_bounds__(NT, 1) recurrence(
    const float* __restrict__ Rz, const float* __restrict__ Ri,
    const float* __restrict__ Rf, const float* __restrict__ Ro,
    const float* __restrict__ brz, const float* __restrict__ bri,
    const float* __restrict__ brf, const float* __restrict__ bro)
{
    extern __shared__ float sm[];
    float* Rs  = sm;                 // 16*512 = 8192 floats
    float* hsm = sm + 8192;          // 32 rows * 516 (pad) = 16512 floats
    float* pre = hsm + 16512;        // 16*33 = 528 floats
    float* csm = pre + 528;          // 128 floats
    float* brs = csm + 128;          // 16 floats

    const int tid = threadIdx.x;
    const int bid = blockIdx.x;
    const int jc  = bid * 4;

    // Snapshot barrier generation base. Consistent across blocks: g_gen can
    // only advance after ALL blocks arrive at a barrier, which is after every
    // block has executed this read.
    __shared__ unsigned s_base;
    if (tid == 0) s_base = g_gen;

    // Load this block's 16 R rows (z0..z3,i0..i3,f0..f3,o0..o3) into smem.
    for (int idx = tid; idx < 16 * 128; idx += NT) {
        const int p = idx >> 7, kq = idx & 127;
        const int gg = p >> 2, c = p & 3;
        const float* Rg = (gg == 0) ? Rz : (gg == 1) ? Ri : (gg == 2) ? Rf : Ro;
        *(float4*)(Rs + p * 512 + kq * 4) =
            *(const float4*)(Rg + (size_t)(jc + c) * HH + kq * 4);
    }
    if (tid < 16) {
        const int gg = tid >> 2, c = tid & 3;
        const float* bg = (gg == 0) ? brz : (gg == 1) ? bri : (gg == 2) ? brf : bro;
        brs[tid] = bg[jc + c];
    }
    csm[tid] = 0.0f;

    // Thread mapping: lane l -> batches (b0, b0+16); warp w + bsel -> pairs p0,p1
    const int w = tid >> 5, l = tid & 31;
    const int b0 = l & 15, bsel = l >> 4;
    const int p0 = w * 4 + bsel * 2, p1 = p0 + 1;
    const int n0 = (p0 >> 2) * 512 + jc + (p0 & 3);
    const int n1 = (p1 >> 2) * 512 + jc + (p1 & 3);

    __syncthreads();
    const unsigned base = s_base;
    const float br0 = brs[p0], br1 = brs[p1];

    const float4* r0p = (const float4*)(Rs + p0 * 512);
    const float4* r1p = (const float4*)(Rs + p1 * 512);
    const float4* h0p = (const float4*)(hsm + b0 * 516);
    const float4* h1p = (const float4*)(hsm + (b0 + 16) * 516);

    for (int s = 0; s < SS; ++s) {
        // Stage h into smem (L2-coherent loads: .cg bypasses stale L1)
        if (s == 0) {
            for (int idx = tid; idx < 16512; idx += NT) hsm[idx] = 0.0f;
        } else {
            const float4* hg4 = (const float4*)g_hbuf[(s - 1) & 1];
            for (int idx = tid; idx < 4096; idx += NT) {
                const int b = idx >> 7, kq = idx & 127;
                float4 v = __ldcg(hg4 + idx);
                *(float4*)(hsm + b * 516 + kq * 4) = v;
            }
        }
        __syncthreads();

        // Pre-activations: acc = G[s] + br + h @ R^T
        const float* Gs = g_G + (size_t)s * (2048 * BB);
        float a00 = Gs[n0 * BB + b0]      + br0;
        float a01 = Gs[n1 * BB + b0]      + br1;
        float a10 = Gs[n0 * BB + b0 + 16] + br0;
        float a11 = Gs[n1 * BB + b0 + 16] + br1;

#pragma unroll 8
        for (int kq = 0; kq < 128; ++kq) {
            const float4 h0 = h0p[kq];
            const float4 h1 = h1p[kq];
            const float4 r0 = r0p[kq];
            const float4 r1 = r1p[kq];
            a00 = fmaf(h0.x, r0.x, a00); a00 = fmaf(h0.y, r0.y, a00);
            a00 = fmaf(h0.z, r0.z, a00); a00 = fmaf(h0.w, r0.w, a00);
            a01 = fmaf(h0.x, r1.x, a01); a01 = fmaf(h0.y, r1.y, a01);
            a01 = fmaf(h0.z, r1.z, a01); a01 = fmaf(h0.w, r1.w, a01);
            a10 = fmaf(h1.x, r0.x, a10); a10 = fmaf(h1.y, r0.y, a10);
            a10 = fmaf(h1.z, r0.z, a10); a10 = fmaf(h1.w, r0.w, a10);
            a11 = fmaf(h1.x, r1.x, a11); a11 = fmaf(h1.y, r1.y, a11);
            a11 = fmaf(h1.z, r1.z, a11); a11 = fmaf(h1.w, r1.w, a11);
        }

        pre[p0 * 33 + b0]      = a00;
        pre[p1 * 33 + b0]      = a01;
        pre[p0 * 33 + b0 + 16] = a10;
        pre[p1 * 33 + b0 + 16] = a11;
        __syncthreads();

        // Gate math + state update: thread -> (hcol = tid>>5, b = tid&31)
        {
            const int b = tid & 31, hc = tid >> 5;
            const float z  = tanhf(pre[hc * 33 + b]);
            const float iv = sigf(pre[(4 + hc) * 33 + b]);
            const float f  = sigf(pre[(8 + hc) * 33 + b]);
            const float o  = sigf(pre[(12 + hc) * 33 + b]);
            const float c  = fmaf(f, csm[tid], z * iv);
            csm[tid] = c;
            const float h = o * tanhf(c);
            g_hbuf[s & 1][b * HH + jc + hc] = h;
            if (s >= SS / 2)
                g_Hist[((size_t)(s - SS / 2) * BB + b) * HH + jc + hc] = h;
        }

        // Generation grid barrier (skip after last step).
        if (s < SS - 1) {
            __threadfence();          // make g_hbuf writes visible device-wide
            __syncthreads();          // all threads of block contributed
            if (tid == 0) {
                const unsigned tgt = base + (unsigned)s + 1u;
                if (atomicAdd(&g_cnt, 1u) == NB - 1u) {
                    // Last arriver: reset count (all have arrived, all others
                    // are spinning on g_gen, nobody touches g_cnt), then release.
                    atomicExch(&g_cnt, 0u);
                    __threadfence();
                    g_gen = tgt;
                } else {
                    while ((int)(g_gen - tgt) < 0) __nanosleep(40);
                    __threadfence();  // acquire: order subsequent reads
                }
            }
            __syncthreads();
        }
    }
    // Launch-exit state: g_cnt == 0, g_gen == base + SS - 1  (replay-safe).
}

// ---------------------------------------------------------------------------
// Output GEMM: out[b][s'][o] = Hist[s'][b][:] . Wl[o][:] + bl[o]
// M = 16384 (m = s'*32+b), N = 512, K = 512.
__global__ void __launch_bounds__(256) output_gemm(
    const float* __restrict__ Wl, const float* __restrict__ bl,
    float* __restrict__ out)
{
    constexpr int BM = 128, BN = 128, BK = 8, TM = 8, TN = 8;
    __shared__ float As[BK][BM + 4];
    __shared__ float Bs[BK][BN + 4];

    const int bx = blockIdx.x;   // 0..3
    const int by = blockIdx.y;   // 0..127
    const int m0 = by * BM;
    const int n0g = bx * BN;

    const int tid  = threadIdx.x;
    const int arow = tid >> 1, acol = (tid & 1) * 4;
    const int brow = tid >> 1, bcol = (tid & 1) * 4;
    const int tx = tid & 15, ty = tid >> 4;
    const int tm0 = ty * TM, tn0 = tx * TN;

    const float* aptr = g_Hist + (size_t)(m0 + arow) * HH;
    const float* bptr = Wl + (size_t)(n0g + brow) * HH;

    float acc[TM][TN];
#pragma unroll
    for (int i = 0; i < TM; i++)
#pragma unroll
        for (int j = 0; j < TN; j++) acc[i][j] = 0.0f;

    for (int k0 = 0; k0 < HH; k0 += BK) {
        float4 av = *(const float4*)(aptr + k0 + acol);
        float4 bv = *(const float4*)(bptr + k0 + bcol);
        As[acol + 0][arow] = av.x; As[acol + 1][arow] = av.y;
        As[acol + 2][arow] = av.z; As[acol + 3][arow] = av.w;
        Bs[bcol + 0][brow] = bv.x; Bs[bcol + 1][brow] = bv.y;
        Bs[bcol + 2][brow] = bv.z; Bs[bcol + 3][brow] = bv.w;
        __syncthreads();
#pragma unroll
        for (int k = 0; k < BK; k++) {
            float ra[TM], rb[TN];
            *(float4*)(ra)     = *(const float4*)(&As[k][tm0]);
            *(float4*)(ra + 4) = *(const float4*)(&As[k][tm0 + 4]);
            *(float4*)(rb)     = *(const float4*)(&Bs[k][tn0]);
            *(float4*)(rb + 4) = *(const float4*)(&Bs[k][tn0 + 4]);
#pragma unroll
            for (int i = 0; i < TM; i++)
#pragma unroll
                for (int j = 0; j < TN; j++)
                    acc[i][j] = fmaf(ra[i], rb[j], acc[i][j]);
        }
        __syncthreads();
    }

    // out layout [b][s'][o]; 8 consecutive m -> same s', consecutive b.
    const int sp = (m0 + tm0) >> 5;
    const int bB = (m0 + tm0) & 31;
#pragma unroll
    for (int j = 0; j < TN; j++) {
        const int n = n0g + tn0 + j;
        const float bv = bl[n];
#pragma unroll
        for (int i = 0; i < TM; i++) {
            out[((size_t)(bB + i) * (SS / 2) + sp) * II + n] = acc[i][j] + bv;
        }
    }
}

// ---------------------------------------------------------------------------
extern "C" void kernel_launch(void* const* d_in, const int* in_sizes, int n_in,
                              void* d_out, int out_size)
{
    const float* x   = (const float*)d_in[0];
    const float* Wz  = (const float*)d_in[1];  const float* bz  = (const float*)d_in[2];
    const float* Wi  = (const float*)d_in[3];  const float* bi  = (const float*)d_in[4];
    const float* Wf  = (const float*)d_in[5];  const float* bf  = (const float*)d_in[6];
    const float* Wo  = (const float*)d_in[7];  const float* bo  = (const float*)d_in[8];
    const float* Rz  = (const float*)d_in[9];  const float* brz = (const float*)d_in[10];
    const float* Ri  = (const float*)d_in[11]; const float* bri = (const float*)d_in[12];
    const float* Rf  = (const float*)d_in[13]; const float* brf = (const float*)d_in[14];
    const float* Ro  = (const float*)d_in[15]; const float* bro = (const float*)d_in[16];
    const float* Wl  = (const float*)d_in[17]; const float* bl  = (const float*)d_in[18];
    float* out = (float*)d_out;

    // 1) Input projections -> g_G
    input_gemm<<<dim3(16, 256), 256>>>(x, Wz, Wi, Wf, Wo, bz, bi, bf, bo);

    // 2) Persistent sequential recurrence -> g_Hist (and g_hbuf scratch)
    const size_t smem = (8192 + 16512 + 528 + 128 + 16) * sizeof(float);
    cudaFuncSetAttribute(recurrence, cudaFuncAttributeMaxDynamicSharedMemorySize, (int)smem);
    recurrence<<<NB, NT, smem>>>(Rz, Ri, Rf, Ro, brz, bri, brf, bro);

    // 3) Output projection -> d_out
    output_gemm<<<dim3(4, 128), 256>>>(Wl, bl, out);
}

// round 3
// speedup vs baseline: 1.3353x; 1.3353x over previous
#include <cuda_runtime.h>
#include <cuda_bf16.h>
#include <cstdint>
#include <cstddef>

// Problem dims (fixed by dataset)
#define BB 32
#define SS 1024
#define II 512
#define HH 512
#define NB 128        // persistent blocks in recurrence
#define NT 128        // threads per recurrence block

// ---------------------------------------------------------------------------
// Scratch (device globals: allocation-free per harness rules)
// G layout: [s][n][b], n = gate*512 + hcol, gate order z,i,f,o.  256 MB.
__device__ float g_G[(size_t)SS * 2048 * BB];
// Hist layout: [s'][b][h] for s' = s-512.  32 MB.
__device__ float g_Hist[(size_t)(SS / 2) * BB * HH];
// Ping-pong hidden state, layout [buf][k][b]  (k = h index, b = batch).
__device__ float g_hbuf[2][HH * BB];
// Generation grid barrier (replay-safe: g_cnt returns to 0, g_gen is monotone)
__device__ unsigned g_cnt;
__device__ volatile unsigned g_gen;

__device__ __forceinline__ float sigf(float x) { return 1.0f / (1.0f + expf(-x)); }

// ---------------------------------------------------------------------------
// Input projection GEMM: G[s][n][b] = sum_i x[b][s][i] * W_g[h][i] + b_g[h]
// M = 32768 (m = s*32+b), N = 2048, K = 512.  Tiles 128x128x8.
// Fragments are split-float4 (4*t and 64+4*t) -> conflict-free LDS.
__global__ void __launch_bounds__(256) input_gemm(
    const float* __restrict__ x,
    const float* __restrict__ Wz, const float* __restrict__ Wi,
    const float* __restrict__ Wf, const float* __restrict__ Wo,
    const float* __restrict__ bz, const float* __restrict__ bi,
    const float* __restrict__ bf, const float* __restrict__ bo)
{
    constexpr int BM = 128, BN = 128, BK = 8;
    __shared__ float As[BK][BM + 4];
    __shared__ float Bs[BK][BN + 4];

    const int bx = blockIdx.x;            // n-tile: 0..15
    const int by = blockIdx.y;            // m-tile: 0..255
    const int gate = bx >> 2;
    const float* W    = (gate == 0) ? Wz : (gate == 1) ? Wi : (gate == 2) ? Wf : Wo;
    const float* bias = (gate == 0) ? bz : (gate == 1) ? bi : (gate == 2) ? bf : bo;
    const int nloc0 = (bx & 3) * BN;      // row offset within this gate's W
    const int m0 = by * BM;

    const int tid  = threadIdx.x;
    const int arow = tid >> 1, acol = (tid & 1) * 4;   // A tile loader
    const int brow = tid >> 1, bcol = (tid & 1) * 4;   // B tile loader
    const int tx = tid & 15, ty = tid >> 4;

    const int am = m0 + arow;
    const float* aptr = x + (size_t)(am & 31) * (SS * II) + (size_t)(am >> 5) * II;
    const float* bptr = W + (size_t)(nloc0 + brow) * II;

    float acc[8][8];
#pragma unroll
    for (int i = 0; i < 8; i++)
#pragma unroll
        for (int j = 0; j < 8; j++) acc[i][j] = 0.0f;

    for (int k0 = 0; k0 < II; k0 += BK) {
        float4 av = *(const float4*)(aptr + k0 + acol);
        float4 bv = *(const float4*)(bptr + k0 + bcol);
        As[acol + 0][arow] = av.x; As[acol + 1][arow] = av.y;
        As[acol + 2][arow] = av.z; As[acol + 3][arow] = av.w;
        Bs[bcol + 0][brow] = bv.x; Bs[bcol + 1][brow] = bv.y;
        Bs[bcol + 2][brow] = bv.z; Bs[bcol + 3][brow] = bv.w;
        __syncthreads();
#pragma unroll
        for (int k = 0; k < BK; k++) {
            float ra[8], rb[8];
            *(float4*)(ra)     = *(const float4*)(&As[k][4 * ty]);
            *(float4*)(ra + 4) = *(const float4*)(&As[k][64 + 4 * ty]);
            *(float4*)(rb)     = *(const float4*)(&Bs[k][4 * tx]);
            *(float4*)(rb + 4) = *(const float4*)(&Bs[k][64 + 4 * tx]);
#pragma unroll
            for (int i = 0; i < 8; i++)
#pragma unroll
                for (int j = 0; j < 8; j++)
                    acc[i][j] = fmaf(ra[i], rb[j], acc[i][j]);
        }
        __syncthreads();
    }

    // Epilogue. m index = s*32 + b; 4 consecutive m (4-aligned) share s.
#pragma unroll
    for (int jh = 0; jh < 2; jh++) {
#pragma unroll
        for (int jj = 0; jj < 4; jj++) {
            const int j = jh * 4 + jj;
            const int n = bx * BN + jh * 64 + 4 * tx + jj;
            const float bv = bias[nloc0 + jh * 64 + 4 * tx + jj];
#pragma unroll
            for (int mh = 0; mh < 2; mh++) {
                const int m = m0 + mh * 64 + 4 * ty;
                const int sB = m >> 5, bB = m & 31;
                float4 v = make_float4(acc[mh * 4 + 0][j] + bv, acc[mh * 4 + 1][j] + bv,
                                       acc[mh * 4 + 2][j] + bv, acc[mh * 4 + 3][j] + bv);
                *(float4*)(g_G + ((size_t)sB * 2048 + n) * BB + bB) = v;
            }
        }
    }
}

// ---------------------------------------------------------------------------
// Persistent recurrence kernel. 128 blocks x 128 threads, 1 block/SM.
// Block bid owns H-columns jc..jc+3 for all 4 gates: pairs p = g*4+c.
// Warps own k-quarters; lanes do 4p x 4b outer products per k.
// h ping-pong in g_hbuf[buf][k][b]; one generation grid-barrier per step.
__global__ void __launch_bounds__(NT, 1) recurrence(
    const float* __restrict__ Rz, const float* __restrict__ Ri,
    const float* __restrict__ Rf, const float* __restrict__ Ro,
    const float* __restrict__ brz, const float* __restrict__ bri,
    const float* __restrict__ brf, const float* __restrict__ bro)
{
    extern __shared__ float sm[];
    float* rs  = sm;                  // [512][16] transposed R : 8192
    float* hsm = sm + 8192;           // [512][36] h staged      : 18432
    float* red = hsm + 18432;         // [4][16][33] partials    : 2112
    float* csm = red + 2112;          // 128 cell states
    float* brs = csm + 128;           // 16 recurrent biases

    const int tid  = threadIdx.x;
    const int bid  = blockIdx.x;
    const int jc   = bid * 4;
    const int w    = tid >> 5;        // warp = k-quarter
    const int lane = tid & 31;

    __shared__ unsigned s_base;
    if (tid == 0) s_base = g_gen;     // consistent snapshot (see R1 notes)

    // rs[k*16 + p] = R_g[jc+c][k],  p = g*4+c
    for (int idx = tid; idx < 8192; idx += NT) {
        const int p = idx & 15, k = idx >> 4;
        const int g = p >> 2, c = p & 3;
        const float* Rg = (g == 0) ? Rz : (g == 1) ? Ri : (g == 2) ? Rf : Ro;
        rs[idx] = Rg[(size_t)(jc + c) * HH + k];
    }
    if (tid < 16) {
        const int g = tid >> 2, c = tid & 3;
        const float* bg = (g == 0) ? brz : (g == 1) ? bri : (g == 2) ? brf : bro;
        brs[tid] = bg[jc + c];
    }
    csm[tid] = 0.0f;
    __syncthreads();
    const unsigned base = s_base;

    // Compute-phase lane roles
    const int p_grp = lane >> 3;      // 0..3
    const int b_grp = lane & 7;       // 0..7
    const float* rq = rs + (size_t)(w * 128) * 16 + 4 * p_grp;
    const float* hq = hsm + (size_t)(w * 128) * 36 + 4 * b_grp;
    // Gate-phase lane roles
    const int c_ = w, b_ = lane;

    for (int s = 0; s < SS; ++s) {
        // Prefetch this thread's 4 G values (DRAM latency hides under FFMA)
        const float* Gs = g_G + (size_t)s * (2048 * BB);
        const float gv0 = Gs[(0 * 512 + jc + c_) * BB + b_];
        const float gv1 = Gs[(1 * 512 + jc + c_) * BB + b_];
        const float gv2 = Gs[(2 * 512 + jc + c_) * BB + b_];
        const float gv3 = Gs[(3 * 512 + jc + c_) * BB + b_];

        // Stage this warp's k-quarter of h: g_hbuf[k][b] -> hsm[k][b] (pitch 36)
        if (s == 0) {
            const float4 z4 = make_float4(0.f, 0.f, 0.f, 0.f);
#pragma unroll 8
            for (int i = 0; i < 32; i++) {
                const int idx = w * 1024 + i * 32 + lane;   // float4 id: k*8+bq
                const int k = idx >> 3, bq = idx & 7;
                *(float4*)&hsm[k * 36 + 4 * bq] = z4;
            }
        } else {
            const float4* hb = (const float4*)g_hbuf[(s - 1) & 1];
#pragma unroll 8
            for (int i = 0; i < 32; i++) {
                const int idx = w * 1024 + i * 32 + lane;
                const int k = idx >> 3, bq = idx & 7;
                float4 v = __ldcg(hb + idx);
                *(float4*)&hsm[k * 36 + 4 * bq] = v;
            }
        }
        __syncwarp();

        // Outer-product accumulation over this warp's 128 k values
        float acc[4][4];
#pragma unroll
        for (int i = 0; i < 4; i++)
#pragma unroll
            for (int j = 0; j < 4; j++) acc[i][j] = 0.0f;

#pragma unroll 4
        for (int kk = 0; kk < 128; kk++) {
            const float4 h4 = *(const float4*)(hq + kk * 36);
            const float4 r4 = *(const float4*)(rq + kk * 16);
            acc[0][0] = fmaf(r4.x, h4.x, acc[0][0]);
            acc[0][1] = fmaf(r4.x, h4.y, acc[0][1]);
            acc[0][2] = fmaf(r4.x, h4.z, acc[0][2]);
            acc[0][3] = fmaf(r4.x, h4.w, acc[0][3]);
            acc[1][0] = fmaf(r4.y, h4.x, acc[1][0]);
            acc[1][1] = fmaf(r4.y, h4.y, acc[1][1]);
            acc[1][2] = fmaf(r4.y, h4.z, acc[1][2]);
            acc[1][3] = fmaf(r4.y, h4.w, acc[1][3]);
            acc[2][0] = fmaf(r4.z, h4.x, acc[2][0]);
            acc[2][1] = fmaf(r4.z, h4.y, acc[2][1]);
            acc[2][2] = fmaf(r4.z, h4.z, acc[2][2]);
            acc[2][3] = fmaf(r4.z, h4.w, acc[2][3]);
            acc[3][0] = fmaf(r4.w, h4.x, acc[3][0]);
            acc[3][1] = fmaf(r4.w, h4.y, acc[3][1]);
            acc[3][2] = fmaf(r4.w, h4.z, acc[3][2]);
            acc[3][3] = fmaf(r4.w, h4.w, acc[3][3]);
        }

        // Write partial sums: red[w][p][b], pitch 33
#pragma unroll
        for (int pp = 0; pp < 4; pp++)
#pragma unroll
            for (int bb = 0; bb < 4; bb++)
                red[(w * 16 + 4 * p_grp + pp) * 33 + 4 * b_grp + bb] = acc[pp][bb];
        __syncthreads();

        // Gate phase: warp w owns hcol c_=w, lane owns batch b_
        float pz = gv0 + brs[0 + c_];
        float pi = gv1 + brs[4 + c_];
        float pf = gv2 + brs[8 + c_];
        float po = gv3 + brs[12 + c_];
#pragma unroll
        for (int wp = 0; wp < 4; wp++) {
            pz += red[(wp * 16 + 0  + c_) * 33 + b_];
            pi += red[(wp * 16 + 4  + c_) * 33 + b_];
            pf += red[(wp * 16 + 8  + c_) * 33 + b_];
            po += red[(wp * 16 + 12 + c_) * 33 + b_];
        }
        const float z  = tanhf(pz);
        const float iv = sigf(pi);
        const float f  = sigf(pf);
        const float o  = sigf(po);
        const float cc = fmaf(f, csm[tid], z * iv);
        csm[tid] = cc;
        const float h = o * tanhf(cc);
        g_hbuf[s & 1][(jc + c_) * BB + b_] = h;      // [k][b] -> coalesced
        if (s >= SS / 2)
            g_Hist[((size_t)(s - SS / 2) * BB + b_) * HH + jc + c_] = h;

        // Generation grid barrier (skip after last step).
        if (s < SS - 1) {
            __threadfence();
            __syncthreads();
            if (tid == 0) {
                const unsigned tgt = base + (unsigned)s + 1u;
                if (atomicAdd(&g_cnt, 1u) == NB - 1u) {
                    atomicExch(&g_cnt, 0u);
                    __threadfence();
                    g_gen = tgt;
                } else {
                    while ((int)(g_gen - tgt) < 0) __nanosleep(32);
                    __threadfence();
                }
            }
            __syncthreads();
        }
    }
    // Launch-exit state: g_cnt == 0, g_gen == base + SS - 1  (replay-safe).
}

// ---------------------------------------------------------------------------
// Output GEMM: out[b][s'][o] = Hist[s'][b][:] . Wl[o][:] + bl[o]
// M = 16384 (m = s'*32+b), N = 512, K = 512.  Conflict-free fragments.
__global__ void __launch_bounds__(256) output_gemm(
    const float* __restrict__ Wl, const float* __restrict__ bl,
    float* __restrict__ out)
{
    constexpr int BM = 128, BN = 128, BK = 8;
    __shared__ float As[BK][BM + 4];
    __shared__ float Bs[BK][BN + 4];

    const int bx = blockIdx.x;   // 0..3
    const int by = blockIdx.y;   // 0..127
    const int m0 = by * BM;
    const int n0g = bx * BN;

    const int tid  = threadIdx.x;
    const int arow = tid >> 1, acol = (tid & 1) * 4;
    const int brow = tid >> 1, bcol = (tid & 1) * 4;
    const int tx = tid & 15, ty = tid >> 4;

    const float* aptr = g_Hist + (size_t)(m0 + arow) * HH;
    const float* bptr = Wl + (size_t)(n0g + brow) * HH;

    float acc[8][8];
#pragma unroll
    for (int i = 0; i < 8; i++)
#pragma unroll
        for (int j = 0; j < 8; j++) acc[i][j] = 0.0f;

    for (int k0 = 0; k0 < HH; k0 += BK) {
        float4 av = *(const float4*)(aptr + k0 + acol);
        float4 bv = *(const float4*)(bptr + k0 + bcol);
        As[acol + 0][arow] = av.x; As[acol + 1][arow] = av.y;
        As[acol + 2][arow] = av.z; As[acol + 3][arow] = av.w;
        Bs[bcol + 0][brow] = bv.x; Bs[bcol + 1][brow] = bv.y;
        Bs[bcol + 2][brow] = bv.z; Bs[bcol + 3][brow] = bv.w;
        __syncthreads();
#pragma unroll
        for (int k = 0; k < BK; k++) {
            float ra[8], rb[8];
            *(float4*)(ra)     = *(const float4*)(&As[k][4 * ty]);
            *(float4*)(ra + 4) = *(const float4*)(&As[k][64 + 4 * ty]);
            *(float4*)(rb)     = *(const float4*)(&Bs[k][4 * tx]);
            *(float4*)(rb + 4) = *(const float4*)(&Bs[k][64 + 4 * tx]);
#pragma unroll
            for (int i = 0; i < 8; i++)
#pragma unroll
                for (int j = 0; j < 8; j++)
                    acc[i][j] = fmaf(ra[i], rb[j], acc[i][j]);
        }
        __syncthreads();
    }

    // out layout [b][s'][o]; vector over o (4 consecutive n).
#pragma unroll
    for (int i = 0; i < 8; i++) {
        const int m = m0 + (i >> 2) * 64 + 4 * ty + (i & 3);
        const int sp = m >> 5, bB = m & 31;
#pragma unroll
        for (int jh = 0; jh < 2; jh++) {
            const int n = n0g + jh * 64 + 4 * tx;
            float4 v = make_float4(acc[i][jh * 4 + 0] + bl[n + 0],
                                   acc[i][jh * 4 + 1] + bl[n + 1],
                                   acc[i][jh * 4 + 2] + bl[n + 2],
                                   acc[i][jh * 4 + 3] + bl[n + 3]);
            *(float4*)(out + ((size_t)bB * (SS / 2) + sp) * II + n) = v;
        }
    }
}

// ---------------------------------------------------------------------------
extern "C" void kernel_launch(void* const* d_in, const int* in_sizes, int n_in,
                              void* d_out, int out_size)
{
    const float* x   = (const float*)d_in[0];
    const float* Wz  = (const float*)d_in[1];  const float* bz  = (const float*)d_in[2];
    const float* Wi  = (const float*)d_in[3];  const float* bi  = (const float*)d_in[4];
    const float* Wf  = (const float*)d_in[5];  const float* bf  = (const float*)d_in[6];
    const float* Wo  = (const float*)d_in[7];  const float* bo  = (const float*)d_in[8];
    const float* Rz  = (const float*)d_in[9];  const float* brz = (const float*)d_in[10];
    const float* Ri  = (const float*)d_in[11]; const float* bri = (const float*)d_in[12];
    const float* Rf  = (const float*)d_in[13]; const float* brf = (const float*)d_in[14];
    const float* Ro  = (const float*)d_in[15]; const float* bro = (const float*)d_in[16];
    const float* Wl  = (const float*)d_in[17]; const float* bl  = (const float*)d_in[18];
    float* out = (float*)d_out;

    // 1) Input projections -> g_G
    input_gemm<<<dim3(16, 256), 256>>>(x, Wz, Wi, Wf, Wo, bz, bi, bf, bo);

    // 2) Persistent sequential recurrence -> g_Hist (and g_hbuf scratch)
    const size_t smem = (8192 + 18432 + 2112 + 128 + 16) * sizeof(float);
    cudaFuncSetAttribute(recurrence, cudaFuncAttributeMaxDynamicSharedMemorySize, (int)smem);
    recurrence<<<NB, NT, smem>>>(Rz, Ri, Rf, Ro, brz, bri, brf, bro);

    // 3) Output projection -> d_out
    output_gemm<<<dim3(4, 128), 256>>>(Wl, bl, out);
}

// round 4
// speedup vs baseline: 1.4229x; 1.0656x over previous
#include <cuda_runtime.h>
#include <cuda_bf16.h>
#include <cstdint>
#include <cstddef>

// Problem dims (fixed by dataset)
#define BB 32
#define SS 1024
#define II 512
#define HH 512
#define NB 128        // persistent blocks in recurrence
#define NT 128        // threads per recurrence block

// ---------------------------------------------------------------------------
// Scratch (device globals: allocation-free per harness rules)
// G layout: [s][n][b], n = gate*512 + hcol, gate order z,i,f,o.  256 MB.
__device__ float g_G[(size_t)SS * 2048 * BB];
// Hist layout: [s'][b][h] for s' = s-512.  32 MB.
__device__ float g_Hist[(size_t)(SS / 2) * BB * HH];
// Ping-pong hidden state, layout [buf][k][b]  (k = h index, b = batch).
__device__ float g_hbuf[2][HH * BB];
// Generation grid barrier (replay-safe: g_cnt returns to 0, g_gen is monotone)
__device__ unsigned g_cnt;
__device__ volatile unsigned g_gen;

__device__ __forceinline__ float sigf(float x) { return 1.0f / (1.0f + expf(-x)); }

// ---------------------------------------------------------------------------
// Input projection GEMM: G[s][n][b] = sum_i x[b][s][i] * W_g[h][i] + b_g[h]
// M = 32768 (m = s*32+b), N = 2048, K = 512.  Tiles 128x128x8.
// Register-prefetch double buffering hides GMEM latency under compute.
__global__ void __launch_bounds__(256, 2) input_gemm(
    const float* __restrict__ x,
    const float* __restrict__ Wz, const float* __restrict__ Wi,
    const float* __restrict__ Wf, const float* __restrict__ Wo,
    const float* __restrict__ bz, const float* __restrict__ bi,
    const float* __restrict__ bf, const float* __restrict__ bo)
{
    constexpr int BM = 128, BN = 128, BK = 8;
    __shared__ float As[BK][BM + 4];
    __shared__ float Bs[BK][BN + 4];

    const int bx = blockIdx.x;            // n-tile: 0..15
    const int by = blockIdx.y;            // m-tile: 0..255
    const int gate = bx >> 2;
    const float* W    = (gate == 0) ? Wz : (gate == 1) ? Wi : (gate == 2) ? Wf : Wo;
    const float* bias = (gate == 0) ? bz : (gate == 1) ? bi : (gate == 2) ? bf : bo;
    const int nloc0 = (bx & 3) * BN;      // row offset within this gate's W
    const int m0 = by * BM;

    const int tid  = threadIdx.x;
    const int arow = tid >> 1, acol = (tid & 1) * 4;   // A tile loader
    const int brow = tid >> 1, bcol = (tid & 1) * 4;   // B tile loader
    const int tx = tid & 15, ty = tid >> 4;

    const int am = m0 + arow;
    const float* apk = x + (size_t)(am & 31) * (SS * II) + (size_t)(am >> 5) * II + acol;
    const float* bpk = W + (size_t)(nloc0 + brow) * II + bcol;

    float acc[8][8];
#pragma unroll
    for (int i = 0; i < 8; i++)
#pragma unroll
        for (int j = 0; j < 8; j++) acc[i][j] = 0.0f;

    float4 av = *(const float4*)(apk);
    float4 bv = *(const float4*)(bpk);

    for (int k0 = 0; k0 < II; k0 += BK) {
        As[acol + 0][arow] = av.x; As[acol + 1][arow] = av.y;
        As[acol + 2][arow] = av.z; As[acol + 3][arow] = av.w;
        Bs[bcol + 0][brow] = bv.x; Bs[bcol + 1][brow] = bv.y;
        Bs[bcol + 2][brow] = bv.z; Bs[bcol + 3][brow] = bv.w;
        __syncthreads();
        if (k0 + BK < II) {                       // prefetch next tile
            av = *(const float4*)(apk + k0 + BK);
            bv = *(const float4*)(bpk + k0 + BK);
        }
#pragma unroll
        for (int k = 0; k < BK; k++) {
            float ra[8], rb[8];
            *(float4*)(ra)     = *(const float4*)(&As[k][4 * ty]);
            *(float4*)(ra + 4) = *(const float4*)(&As[k][64 + 4 * ty]);
            *(float4*)(rb)     = *(const float4*)(&Bs[k][4 * tx]);
            *(float4*)(rb + 4) = *(const float4*)(&Bs[k][64 + 4 * tx]);
#pragma unroll
            for (int i = 0; i < 8; i++)
#pragma unroll
                for (int j = 0; j < 8; j++)
                    acc[i][j] = fmaf(ra[i], rb[j], acc[i][j]);
        }
        __syncthreads();
    }

    // Epilogue. m index = s*32 + b; 4 consecutive m (4-aligned) share s.
#pragma unroll
    for (int jh = 0; jh < 2; jh++) {
#pragma unroll
        for (int jj = 0; jj < 4; jj++) {
            const int j = jh * 4 + jj;
            const int n = bx * BN + jh * 64 + 4 * tx + jj;
            const float bvv = bias[nloc0 + jh * 64 + 4 * tx + jj];
#pragma unroll
            for (int mh = 0; mh < 2; mh++) {
                const int m = m0 + mh * 64 + 4 * ty;
                const int sB = m >> 5, bB = m & 31;
                float4 v = make_float4(acc[mh * 4 + 0][j] + bvv, acc[mh * 4 + 1][j] + bvv,
                                       acc[mh * 4 + 2][j] + bvv, acc[mh * 4 + 3][j] + bvv);
                *(float4*)(g_G + ((size_t)sB * 2048 + n) * BB + bB) = v;
            }
        }
    }
}

// ---------------------------------------------------------------------------
// Persistent recurrence. 128 blocks x 128 threads, 1 block/SM.
// Block = (hcol-group j = bid>>1, batch-half = bid&1): owns 8 hcols x 4 gates
// (32 p-rows) for 16 batches.  8x8 micro-tiles, 16-way k-split, smem reduce.
// h ping-pong in g_hbuf[buf][k][b]; one generation grid-barrier per step.
__global__ void __launch_bounds__(NT, 1) recurrence(
    const float* __restrict__ Rz, const float* __restrict__ Ri,
    const float* __restrict__ Rf, const float* __restrict__ Ro,
    const float* __restrict__ brz, const float* __restrict__ bri,
    const float* __restrict__ brf, const float* __restrict__ bro)
{
    extern __shared__ float sm[];
    float* rs  = sm;                  // [512][32]  R stream     : 16384
    float* hs  = sm + 16384;          // [512][16]  h staged     : 8192
    float* red = sm + 24576;          // [16][16][33] partials   : 8448
    float* csm = red + 8448;          // 128 cell states
    float* brs = csm + 128;           // 32 recurrent biases (p = g*8+c)

    const int tid = threadIdx.x;
    const int bid = blockIdx.x;
    const int jc  = (bid >> 1) * 8;   // hcol base (8 cols)
    const int b0g = (bid & 1) * 16;   // batch base (16 batches)
    const int w = tid >> 5, l = tid & 31;

    __shared__ unsigned s_base;
    if (tid == 0) s_base = g_gen;     // consistent snapshot (see R1 notes)

    // rs[k*32 + p] = R_g[jc+c][k],  p = g*8 + c.
    // Read k-major (coalesced float4), write p-major (conflict-free).
    for (int i = 0; i < 32; i++) {
        const int idx = i * 128 + tid;          // 4096 groups: (k4, p)
        const int p = idx & 31, k4 = idx >> 5;
        const int g = p >> 3, c = p & 7;
        const float* Rg = (g == 0) ? Rz : (g == 1) ? Ri : (g == 2) ? Rf : Ro;
        float4 v = *(const float4*)(Rg + (size_t)(jc + c) * HH + k4 * 4);
        rs[(k4 * 4 + 0) * 32 + p] = v.x;
        rs[(k4 * 4 + 1) * 32 + p] = v.y;
        rs[(k4 * 4 + 2) * 32 + p] = v.z;
        rs[(k4 * 4 + 3) * 32 + p] = v.w;
    }
    if (tid < 32) {
        const int g = tid >> 3, c = tid & 7;
        const float* bg = (g == 0) ? brz : (g == 1) ? bri : (g == 2) ? brf : bro;
        brs[tid] = bg[jc + c];
    }
    csm[tid] = 0.0f;
    __syncthreads();
    const unsigned base = s_base;

    // Compute-phase lane roles: kg = k-16th (warp-local), gg = gate, bg = b-half
    const int kg = w * 4 + (l >> 3);  // 0..15
    const int gg = l & 3;             // p-group: p = gg*8 + pi
    const int bg = (l >> 2) & 1;      // b-group: b = bg*8 + bj
    const float* rq = rs + (size_t)(kg * 32) * 32 + gg * 8;
    const float* hq = hs + (size_t)(kg * 32) * 16 + bg * 8;
    // Cell roles: thread -> (hcol c_, batch b_)
    const int c_ = tid >> 4;          // 0..7
    const int b_ = tid & 15;          // 0..15

    for (int s = 0; s < SS; ++s) {
        // Prefetch this thread's 4 G values (latency hides under staging+mm)
        const float* Gs = g_G + (size_t)s * (2048 * BB);
        const float gv0 = Gs[(0 * 512 + jc + c_) * BB + b0g + b_];
        const float gv1 = Gs[(1 * 512 + jc + c_) * BB + b0g + b_];
        const float gv2 = Gs[(2 * 512 + jc + c_) * BB + b0g + b_];
        const float gv3 = Gs[(3 * 512 + jc + c_) * BB + b0g + b_];

        // Warp w stages its own k range [w*128, w*128+128) of h (16 batches).
        if (s == 0) {
            const float4 z4 = make_float4(0.f, 0.f, 0.f, 0.f);
#pragma unroll 4
            for (int i = 0; i < 16; i++) {
                const int idx = i * 32 + l;     // (k - w*128)*4 + x4
                const int k = w * 128 + (idx >> 2), x4 = idx & 3;
                *(float4*)&hs[k * 16 + x4 * 4] = z4;
            }
        } else {
            const float* hb = g_hbuf[(s - 1) & 1];
#pragma unroll 4
            for (int i = 0; i < 16; i++) {
                const int idx = i * 32 + l;
                const int k = w * 128 + (idx >> 2), x4 = idx & 3;
                float4 v = __ldcg((const float4*)(hb + k * 32 + b0g + x4 * 4));
                *(float4*)&hs[k * 16 + x4 * 4] = v;
            }
        }
        __syncwarp();

        // 8x8 outer-product over this thread's 32 k values
        float acc[8][8];
#pragma unroll
        for (int i = 0; i < 8; i++)
#pragma unroll
            for (int j = 0; j < 8; j++) acc[i][j] = 0.0f;

        const float* rp = rq;
        const float* hp = hq;
#pragma unroll 4
        for (int kk = 0; kk < 32; kk++) {
            float rr[8], hh[8];
            *(float4*)(rr)     = *(const float4*)(rp);
            *(float4*)(rr + 4) = *(const float4*)(rp + 4);
            *(float4*)(hh)     = *(const float4*)(hp);
            *(float4*)(hh + 4) = *(const float4*)(hp + 4);
#pragma unroll
            for (int i = 0; i < 8; i++)
#pragma unroll
                for (int j = 0; j < 8; j++)
                    acc[i][j] = fmaf(rr[i], hh[j], acc[i][j]);
            rp += 32; hp += 16;
        }

        // Partials: red[kg][b][p], pitch 33 over p
#pragma unroll
        for (int pi = 0; pi < 8; pi++)
#pragma unroll
            for (int bj = 0; bj < 8; bj++)
                red[(kg * 16 + bg * 8 + bj) * 33 + gg * 8 + pi] = acc[pi][bj];
        __syncthreads();

        // Gate phase: sum 16 kg partials per gate for cell (c_, b_)
        float pz = gv0 + brs[0 + c_];
        float pi_ = gv1 + brs[8 + c_];
        float pf = gv2 + brs[16 + c_];
        float po = gv3 + brs[24 + c_];
#pragma unroll
        for (int q = 0; q < 16; q++) {
            const float* rr = red + (q * 16 + b_) * 33 + c_;
            pz  += rr[0];
            pi_ += rr[8];
            pf  += rr[16];
            po  += rr[24];
        }
        const float z  = tanhf(pz);
        const float iv = sigf(pi_);
        const float f  = sigf(pf);
        const float o  = sigf(po);
        const float cc = fmaf(f, csm[tid], z * iv);
        csm[tid] = cc;
        const float h = o * tanhf(cc);
        g_hbuf[s & 1][(jc + c_) * BB + b0g + b_] = h;   // [k][b] coalesced
        if (s >= SS / 2)
            g_Hist[((size_t)(s - SS / 2) * BB + b0g + b_) * HH + jc + c_] = h;

        // Generation grid barrier (skip after last step).
        if (s < SS - 1) {
            __threadfence();
            __syncthreads();
            if (tid == 0) {
                const unsigned tgt = base + (unsigned)s + 1u;
                if (atomicAdd(&g_cnt, 1u) == NB - 1u) {
                    atomicExch(&g_cnt, 0u);
                    __threadfence();
                    g_gen = tgt;
                } else {
                    while ((int)(g_gen - tgt) < 0) __nanosleep(32);
                    __threadfence();
                }
            }
            __syncthreads();
        }
    }
    // Launch-exit state: g_cnt == 0, g_gen == base + SS - 1  (replay-safe).
}

// ---------------------------------------------------------------------------
// Output GEMM: out[b][s'][o] = Hist[s'][b][:] . Wl[o][:] + bl[o]
// M = 16384 (m = s'*32+b), N = 512, K = 512.  Prefetch double-buffered.
__global__ void __launch_bounds__(256, 2) output_gemm(
    const float* __restrict__ Wl, const float* __restrict__ bl,
    float* __restrict__ out)
{
    constexpr int BM = 128, BN = 128, BK = 8;
    __shared__ float As[BK][BM + 4];
    __shared__ float Bs[BK][BN + 4];

    const int bx = blockIdx.x;   // 0..3
    const int by = blockIdx.y;   // 0..127
    const int m0 = by * BM;
    const int n0g = bx * BN;

    const int tid  = threadIdx.x;
    const int arow = tid >> 1, acol = (tid & 1) * 4;
    const int brow = tid >> 1, bcol = (tid & 1) * 4;
    const int tx = tid & 15, ty = tid >> 4;

    const float* apk = g_Hist + (size_t)(m0 + arow) * HH + acol;
    const float* bpk = Wl + (size_t)(n0g + brow) * HH + bcol;

    float acc[8][8];
#pragma unroll
    for (int i = 0; i < 8; i++)
#pragma unroll
        for (int j = 0; j < 8; j++) acc[i][j] = 0.0f;

    float4 av = *(const float4*)(apk);
    float4 bv = *(const float4*)(bpk);

    for (int k0 = 0; k0 < HH; k0 += BK) {
        As[acol + 0][arow] = av.x; As[acol + 1][arow] = av.y;
        As[acol + 2][arow] = av.z; As[acol + 3][arow] = av.w;
        Bs[bcol + 0][brow] = bv.x; Bs[bcol + 1][brow] = bv.y;
        Bs[bcol + 2][brow] = bv.z; Bs[bcol + 3][brow] = bv.w;
        __syncthreads();
        if (k0 + BK < HH) {
            av = *(const float4*)(apk + k0 + BK);
            bv = *(const float4*)(bpk + k0 + BK);
        }
#pragma unroll
        for (int k = 0; k < BK; k++) {
            float ra[8], rb[8];
            *(float4*)(ra)     = *(const float4*)(&As[k][4 * ty]);
            *(float4*)(ra + 4) = *(const float4*)(&As[k][64 + 4 * ty]);
            *(float4*)(rb)     = *(const float4*)(&Bs[k][4 * tx]);
            *(float4*)(rb + 4) = *(const float4*)(&Bs[k][64 + 4 * tx]);
#pragma unroll
            for (int i = 0; i < 8; i++)
#pragma unroll
                for (int j = 0; j < 8; j++)
                    acc[i][j] = fmaf(ra[i], rb[j], acc[i][j]);
        }
        __syncthreads();
    }

    // out layout [b][s'][o]; vector over o (4 consecutive n).
#pragma unroll
    for (int i = 0; i < 8; i++) {
        const int m = m0 + (i >> 2) * 64 + 4 * ty + (i & 3);
        const int sp = m >> 5, bB = m & 31;
#pragma unroll
        for (int jh = 0; jh < 2; jh++) {
            const int n = n0g + jh * 64 + 4 * tx;
            float4 v = make_float4(acc[i][jh * 4 + 0] + bl[n + 0],
                                   acc[i][jh * 4 + 1] + bl[n + 1],
                                   acc[i][jh * 4 + 2] + bl[n + 2],
                                   acc[i][jh * 4 + 3] + bl[n + 3]);
            *(float4*)(out + ((size_t)bB * (SS / 2) + sp) * II + n) = v;
        }
    }
}

// ---------------------------------------------------------------------------
extern "C" void kernel_launch(void* const* d_in, const int* in_sizes, int n_in,
                              void* d_out, int out_size)
{
    const float* x   = (const float*)d_in[0];
    const float* Wz  = (const float*)d_in[1];  const float* bz  = (const float*)d_in[2];
    const float* Wi  = (const float*)d_in[3];  const float* bi  = (const float*)d_in[4];
    const float* Wf  = (const float*)d_in[5];  const float* bf  = (const float*)d_in[6];
    const float* Wo  = (const float*)d_in[7];  const float* bo  = (const float*)d_in[8];
    const float* Rz  = (const float*)d_in[9];  const float* brz = (const float*)d_in[10];
    const float* Ri  = (const float*)d_in[11]; const float* bri = (const float*)d_in[12];
    const float* Rf  = (const float*)d_in[13]; const float* brf = (const float*)d_in[14];
    const float* Ro  = (const float*)d_in[15]; const float* bro = (const float*)d_in[16];
    const float* Wl  = (const float*)d_in[17]; const float* bl  = (const float*)d_in[18];
    float* out = (float*)d_out;

    // 1) Input projections -> g_G
    input_gemm<<<dim3(16, 256), 256>>>(x, Wz, Wi, Wf, Wo, bz, bi, bf, bo);

    // 2) Persistent sequential recurrence -> g_Hist (and g_hbuf scratch)
    const size_t smem = (16384 + 8192 + 8448 + 128 + 32) * sizeof(float);
    cudaFuncSetAttribute(recurrence, cudaFuncAttributeMaxDynamicSharedMemorySize, (int)smem);
    recurrence<<<NB, NT, smem>>>(Rz, Ri, Rf, Ro, brz, bri, brf, bro);

    // 3) Output projection -> d_out
    output_gemm<<<dim3(4, 128), 256>>>(Wl, bl, out);
}

// round 6
// speedup vs baseline: 1.5124x; 1.0629x over previous
#include <cuda_runtime.h>
#include <cuda_bf16.h>
#include <cstdint>
#include <cstddef>

// Problem dims (fixed by dataset)
#define BB 32
#define SS 1024
#define II 512
#define HH 512
#define NB 128        // persistent blocks in recurrence
#define NT 128        // threads per recurrence block

// ---------------------------------------------------------------------------
// Scratch (device globals: allocation-free per harness rules)
__device__ float g_G[(size_t)SS * 2048 * BB];          // [s][n][b]
__device__ float g_Hist[(size_t)(SS / 2) * BB * HH];   // [s'][b][h]
__device__ float g_hbuf[2][HH * BB];                   // ping-pong [buf][k][b]
__device__ unsigned g_cnt;
__device__ volatile unsigned g_gen;

__device__ __forceinline__ float sigf(float x) { return 1.0f / (1.0f + expf(-x)); }

// Packed fp32x2 helpers (FFMA2: 2 FMAs per instruction; ptxas never emits it)
__device__ __forceinline__ void ffma2(unsigned long long& d,
                                      unsigned long long a,
                                      unsigned long long b) {
    asm("fma.rn.f32x2 %0, %1, %2, %0;" : "+l"(d) : "l"(a), "l"(b));
}
__device__ __forceinline__ unsigned long long splat2(float x) {
    unsigned long long r;
    asm("mov.b64 %0, {%1, %1};" : "=l"(r) : "f"(x));
    return r;
}
__device__ __forceinline__ float2 unpack2(unsigned long long v) {
    float2 f;
    asm("mov.b64 {%0, %1}, %2;" : "=f"(f.x), "=f"(f.y) : "l"(v));
    return f;
}

// ---------------------------------------------------------------------------
// Input projection GEMM: G[s][n][b] = sum_i x[b][s][i] * W_g[h][i] + b_g[h]
// M = 32768 (m = s*32+b), N = 2048, K = 512.  Tiles 128x128x8, FFMA2 core.
__global__ void __launch_bounds__(256, 2) input_gemm(
    const float* __restrict__ x,
    const float* __restrict__ Wz, const float* __restrict__ Wi,
    const float* __restrict__ Wf, const float* __restrict__ Wo,
    const float* __restrict__ bz, const float* __restrict__ bi,
    const float* __restrict__ bf, const float* __restrict__ bo)
{
    constexpr int BM = 128, BN = 128, BK = 8;
    __shared__ float As[BK][BM + 4];
    __shared__ float Bs[BK][BN + 4];

    const int bx = blockIdx.x;            // n-tile: 0..15
    const int by = blockIdx.y;            // m-tile: 0..255
    const int gate = bx >> 2;
    const float* W    = (gate == 0) ? Wz : (gate == 1) ? Wi : (gate == 2) ? Wf : Wo;
    const float* bias = (gate == 0) ? bz : (gate == 1) ? bi : (gate == 2) ? bf : bo;
    const int nloc0 = (bx & 3) * BN;
    const int m0 = by * BM;

    const int tid  = threadIdx.x;
    const int arow = tid >> 1, acol = (tid & 1) * 4;
    const int brow = tid >> 1, bcol = (tid & 1) * 4;
    const int tx = tid & 15, ty = tid >> 4;

    const int am = m0 + arow;
    const float* apk = x + (size_t)(am & 31) * (SS * II) + (size_t)(am >> 5) * II + acol;
    const float* bpk = W + (size_t)(nloc0 + brow) * II + bcol;

    unsigned long long acc2[8][4];
#pragma unroll
    for (int i = 0; i < 8; i++)
#pragma unroll
        for (int j = 0; j < 4; j++) acc2[i][j] = 0ULL;

    float4 av = *(const float4*)(apk);
    float4 bv = *(const float4*)(bpk);

    for (int k0 = 0; k0 < II; k0 += BK) {
        As[acol + 0][arow] = av.x; As[acol + 1][arow] = av.y;
        As[acol + 2][arow] = av.z; As[acol + 3][arow] = av.w;
        Bs[bcol + 0][brow] = bv.x; Bs[bcol + 1][brow] = bv.y;
        Bs[bcol + 2][brow] = bv.z; Bs[bcol + 3][brow] = bv.w;
        __syncthreads();
        if (k0 + BK < II) {                       // prefetch next tile
            av = *(const float4*)(apk + k0 + BK);
            bv = *(const float4*)(bpk + k0 + BK);
        }
#pragma unroll
        for (int k = 0; k < BK; k++) {
            float ra[8];
            *(float4*)(ra)     = *(const float4*)(&As[k][4 * ty]);
            *(float4*)(ra + 4) = *(const float4*)(&As[k][64 + 4 * ty]);
            const ulonglong2 b01 = *(const ulonglong2*)(&Bs[k][4 * tx]);
            const ulonglong2 b23 = *(const ulonglong2*)(&Bs[k][64 + 4 * tx]);
#pragma unroll
            for (int i = 0; i < 8; i++) {
                const unsigned long long a2 = splat2(ra[i]);
                ffma2(acc2[i][0], a2, b01.x);
                ffma2(acc2[i][1], a2, b01.y);
                ffma2(acc2[i][2], a2, b23.x);
                ffma2(acc2[i][3], a2, b23.y);
            }
        }
        __syncthreads();
    }

    // Unpack and store.  acc[i][j] = unpack(acc2[i][j>>1])[j&1]
    float acc[8][8];
#pragma unroll
    for (int i = 0; i < 8; i++)
#pragma unroll
        for (int jp = 0; jp < 4; jp++) {
            float2 f = unpack2(acc2[i][jp]);
            acc[i][2 * jp] = f.x; acc[i][2 * jp + 1] = f.y;
        }

#pragma unroll
    for (int jh = 0; jh < 2; jh++) {
#pragma unroll
        for (int jj = 0; jj < 4; jj++) {
            const int j = jh * 4 + jj;
            const int n = bx * BN + jh * 64 + 4 * tx + jj;
            const float bvv = bias[nloc0 + jh * 64 + 4 * tx + jj];
#pragma unroll
            for (int mh = 0; mh < 2; mh++) {
                const int m = m0 + mh * 64 + 4 * ty;
                const int sB = m >> 5, bB = m & 31;
                float4 v = make_float4(acc[mh * 4 + 0][j] + bvv, acc[mh * 4 + 1][j] + bvv,
                                       acc[mh * 4 + 2][j] + bvv, acc[mh * 4 + 3][j] + bvv);
                *(float4*)(g_G + ((size_t)sB * 2048 + n) * BB + bB) = v;
            }
        }
    }
}

// ---------------------------------------------------------------------------
// Persistent recurrence. 128 blocks x 128 threads, 1 block/SM.
// Block = (hcol-group jc = (bid>>1)*8, batch-half b0g = (bid&1)*16).
// 8x8 micro-tiles as FFMA2 (batch packed), 16-way k-split, smem reduce.
__global__ void __launch_bounds__(NT, 1) recurrence(
    const float* __restrict__ Rz, const float* __restrict__ Ri,
    const float* __restrict__ Rf, const float* __restrict__ Ro,
    const float* __restrict__ brz, const float* __restrict__ bri,
    const float* __restrict__ brf, const float* __restrict__ bro)
{
    extern __shared__ float sm[];
    float* rs  = sm;                  // [512][32]  R stream     : 16384
    float* hs  = sm + 16384;          // [512][16]  h staged     : 8192
    float* red = sm + 24576;          // [16][16][33] partials   : 8448
    float* csm = red + 8448;          // 128 cell states
    float* brs = csm + 128;           // 32 recurrent biases (p = g*8+c)

    const int tid = threadIdx.x;
    const int bid = blockIdx.x;
    const int jc  = (bid >> 1) * 8;
    const int b0g = (bid & 1) * 16;
    const int w = tid >> 5, l = tid & 31;

    __shared__ unsigned s_base;
    if (tid == 0) s_base = g_gen;     // consistent snapshot (see R1 notes)

    // rs[k*32 + p] = R_g[jc+c][k],  p = g*8 + c.
    for (int i = 0; i < 32; i++) {
        const int idx = i * 128 + tid;
        const int p = idx & 31, k4 = idx >> 5;
        const int g = p >> 3, c = p & 7;
        const float* Rg = (g == 0) ? Rz : (g == 1) ? Ri : (g == 2) ? Rf : Ro;
        float4 v = *(const float4*)(Rg + (size_t)(jc + c) * HH + k4 * 4);
        rs[(k4 * 4 + 0) * 32 + p] = v.x;
        rs[(k4 * 4 + 1) * 32 + p] = v.y;
        rs[(k4 * 4 + 2) * 32 + p] = v.z;
        rs[(k4 * 4 + 3) * 32 + p] = v.w;
    }
    if (tid < 32) {
        const int g = tid >> 3, c = tid & 7;
        const float* bg = (g == 0) ? brz : (g == 1) ? bri : (g == 2) ? brf : bro;
        brs[tid] = bg[jc + c];
    }
    csm[tid] = 0.0f;
    __syncthreads();
    const unsigned base = s_base;

    // Compute-phase lane roles
    const int kg = w * 4 + (l >> 3);  // 0..15
    const int gg = l & 3;             // p-group
    const int bgp = (l >> 2) & 1;     // b-group
    const float* rq = rs + (size_t)(kg * 32) * 32 + gg * 8;
    const float* hq = hs + (size_t)(kg * 32) * 16 + bgp * 8;
    // Cell roles
    const int c_ = tid >> 4;          // 0..7
    const int b_ = tid & 15;          // 0..15

    // G prefetch for s = 0
    float gv0 = g_G[(0 * 512 + jc + c_) * BB + b0g + b_];
    float gv1 = g_G[(1 * 512 + jc + c_) * BB + b0g + b_];
    float gv2 = g_G[(2 * 512 + jc + c_) * BB + b0g + b_];
    float gv3 = g_G[(3 * 512 + jc + c_) * BB + b0g + b_];

    for (int s = 0; s < SS; ++s) {
        // Warp w stages its own k range [w*128, w*128+128) of h (16 batches).
        if (s == 0) {
            const float4 z4 = make_float4(0.f, 0.f, 0.f, 0.f);
#pragma unroll 4
            for (int i = 0; i < 16; i++) {
                const int idx = i * 32 + l;
                const int k = w * 128 + (idx >> 2), x4 = idx & 3;
                *(float4*)&hs[k * 16 + x4 * 4] = z4;
            }
        } else {
            const float* hb = g_hbuf[(s - 1) & 1];
#pragma unroll 4
            for (int i = 0; i < 16; i++) {
                const int idx = i * 32 + l;
                const int k = w * 128 + (idx >> 2), x4 = idx & 3;
                float4 v = __ldcg((const float4*)(hb + k * 32 + b0g + x4 * 4));
                *(float4*)&hs[k * 16 + x4 * 4] = v;
            }
        }
        __syncwarp();

        // 8(p) x 8(b) outer-product over this thread's 32 k values, FFMA2 on b
        unsigned long long acc2[8][4];
#pragma unroll
        for (int i = 0; i < 8; i++)
#pragma unroll
            for (int j = 0; j < 4; j++) acc2[i][j] = 0ULL;

        const float* rp = rq;
        const float* hp = hq;
#pragma unroll 4
        for (int kk = 0; kk < 32; kk++) {
            float rr[8];
            *(float4*)(rr)     = *(const float4*)(rp);
            *(float4*)(rr + 4) = *(const float4*)(rp + 4);
            const ulonglong2 h01 = *(const ulonglong2*)(hp);
            const ulonglong2 h23 = *(const ulonglong2*)(hp + 4);
#pragma unroll
            for (int i = 0; i < 8; i++) {
                const unsigned long long a2 = splat2(rr[i]);
                ffma2(acc2[i][0], a2, h01.x);
                ffma2(acc2[i][1], a2, h01.y);
                ffma2(acc2[i][2], a2, h23.x);
                ffma2(acc2[i][3], a2, h23.y);
            }
            rp += 32; hp += 16;
        }

        // Partials: red[kg][b][p], pitch 33 over p
#pragma unroll
        for (int pi = 0; pi < 8; pi++)
#pragma unroll
            for (int bj2 = 0; bj2 < 4; bj2++) {
                const float2 f = unpack2(acc2[pi][bj2]);
                red[(kg * 16 + bgp * 8 + 2 * bj2 + 0) * 33 + gg * 8 + pi] = f.x;
                red[(kg * 16 + bgp * 8 + 2 * bj2 + 1) * 33 + gg * 8 + pi] = f.y;
            }
        __syncthreads();

        // Gate phase: sum 16 kg partials per gate for cell (c_, b_)
        float pz = gv0 + brs[0 + c_];
        float pi_ = gv1 + brs[8 + c_];
        float pf = gv2 + brs[16 + c_];
        float po = gv3 + brs[24 + c_];
#pragma unroll
        for (int q = 0; q < 16; q++) {
            const float* rr = red + (q * 16 + b_) * 33 + c_;
            pz  += rr[0];
            pi_ += rr[8];
            pf  += rr[16];
            po  += rr[24];
        }
        const float z  = tanhf(pz);
        const float iv = sigf(pi_);
        const float f  = sigf(pf);
        const float o  = sigf(po);
        const float cc = fmaf(f, csm[tid], z * iv);
        csm[tid] = cc;
        const float h = o * tanhf(cc);
        g_hbuf[s & 1][(jc + c_) * BB + b0g + b_] = h;
        if (s >= SS / 2)
            g_Hist[((size_t)(s - SS / 2) * BB + b0g + b_) * HH + jc + c_] = h;

        // Prefetch next step's G, then grid barrier (latency overlaps spin).
        if (s < SS - 1) {
            const float* Gn = g_G + (size_t)(s + 1) * (2048 * BB);
            const float t0 = Gn[(0 * 512 + jc + c_) * BB + b0g + b_];
            const float t1 = Gn[(1 * 512 + jc + c_) * BB + b0g + b_];
            const float t2 = Gn[(2 * 512 + jc + c_) * BB + b0g + b_];
            const float t3 = Gn[(3 * 512 + jc + c_) * BB + b0g + b_];

            __threadfence();
            __syncthreads();
            if (tid == 0) {
                const unsigned tgt = base + (unsigned)s + 1u;
                if (atomicAdd(&g_cnt, 1u) == NB - 1u) {
                    atomicExch(&g_cnt, 0u);
                    __threadfence();
                    g_gen = tgt;
                } else {
                    while ((int)(g_gen - tgt) < 0) __nanosleep(32);
                    __threadfence();
                }
            }
            __syncthreads();
            gv0 = t0; gv1 = t1; gv2 = t2; gv3 = t3;
        }
    }
    // Launch-exit state: g_cnt == 0, g_gen == base + SS - 1  (replay-safe).
}

// ---------------------------------------------------------------------------
// Output GEMM: out[b][s'][o] = Hist[s'][b][:] . Wl[o][:] + bl[o]
// M = 16384 (m = s'*32+b), N = 512, K = 512.  FFMA2 core.
__global__ void __launch_bounds__(256, 2) output_gemm(
    const float* __restrict__ Wl, const float* __restrict__ bl,
    float* __restrict__ out)
{
    constexpr int BM = 128, BN = 128, BK = 8;
    __shared__ float As[BK][BM + 4];
    __shared__ float Bs[BK][BN + 4];

    const int bx = blockIdx.x;   // 0..3
    const int by = blockIdx.y;   // 0..127
    const int m0 = by * BM;
    const int n0g = bx * BN;

    const int tid  = threadIdx.x;
    const int arow = tid >> 1, acol = (tid & 1) * 4;
    const int brow = tid >> 1, bcol = (tid & 1) * 4;
    const int tx = tid & 15, ty = tid >> 4;

    const float* apk = g_Hist + (size_t)(m0 + arow) * HH + acol;
    const float* bpk = Wl + (size_t)(n0g + brow) * HH + bcol;

    unsigned long long acc2[8][4];
#pragma unroll
    for (int i = 0; i < 8; i++)
#pragma unroll
        for (int j = 0; j < 4; j++) acc2[i][j] = 0ULL;

    float4 av = *(const float4*)(apk);
    float4 bv = *(const float4*)(bpk);

    for (int k0 = 0; k0 < HH; k0 += BK) {
        As[acol + 0][arow] = av.x; As[acol + 1][arow] = av.y;
        As[acol + 2][arow] = av.z; As[acol + 3][arow] = av.w;
        Bs[bcol + 0][brow] = bv.x; Bs[bcol + 1][brow] = bv.y;
        Bs[bcol + 2][brow] = bv.z; Bs[bcol + 3][brow] = bv.w;
        __syncthreads();
        if (k0 + BK < HH) {
            av = *(const float4*)(apk + k0 + BK);
            bv = *(const float4*)(bpk + k0 + BK);
        }
#pragma unroll
        for (int k = 0; k < BK; k++) {
            float ra[8];
            *(float4*)(ra)     = *(const float4*)(&As[k][4 * ty]);
            *(float4*)(ra + 4) = *(const float4*)(&As[k][64 + 4 * ty]);
            const ulonglong2 b01 = *(const ulonglong2*)(&Bs[k][4 * tx]);
            const ulonglong2 b23 = *(const ulonglong2*)(&Bs[k][64 + 4 * tx]);
#pragma unroll
            for (int i = 0; i < 8; i++) {
                const unsigned long long a2 = splat2(ra[i]);
                ffma2(acc2[i][0], a2, b01.x);
                ffma2(acc2[i][1], a2, b01.y);
                ffma2(acc2[i][2], a2, b23.x);
                ffma2(acc2[i][3], a2, b23.y);
            }
        }
        __syncthreads();
    }

    float acc[8][8];
#pragma unroll
    for (int i = 0; i < 8; i++)
#pragma unroll
        for (int jp = 0; jp < 4; jp++) {
            float2 f = unpack2(acc2[i][jp]);
            acc[i][2 * jp] = f.x; acc[i][2 * jp + 1] = f.y;
        }

    // out layout [b][s'][o]; vector over o (4 consecutive n).
#pragma unroll
    for (int i = 0; i < 8; i++) {
        const int m = m0 + (i >> 2) * 64 + 4 * ty + (i & 3);
        const int sp = m >> 5, bB = m & 31;
#pragma unroll
        for (int jh = 0; jh < 2; jh++) {
            const int n = n0g + jh * 64 + 4 * tx;
            float4 v = make_float4(acc[i][jh * 4 + 0] + bl[n + 0],
                                   acc[i][jh * 4 + 1] + bl[n + 1],
                                   acc[i][jh * 4 + 2] + bl[n + 2],
                                   acc[i][jh * 4 + 3] + bl[n + 3]);
            *(float4*)(out + ((size_t)bB * (SS / 2) + sp) * II + n) = v;
        }
    }
}

// ---------------------------------------------------------------------------
extern "C" void kernel_launch(void* const* d_in, const int* in_sizes, int n_in,
                              void* d_out, int out_size)
{
    const float* x   = (const float*)d_in[0];
    const float* Wz  = (const float*)d_in[1];  const float* bz  = (const float*)d_in[2];
    const float* Wi  = (const float*)d_in[3];  const float* bi  = (const float*)d_in[4];
    const float* Wf  = (const float*)d_in[5];  const float* bf  = (const float*)d_in[6];
    const float* Wo  = (const float*)d_in[7];  const float* bo  = (const float*)d_in[8];
    const float* Rz  = (const float*)d_in[9];  const float* brz = (const float*)d_in[10];
    const float* Ri  = (const float*)d_in[11]; const float* bri = (const float*)d_in[12];
    const float* Rf  = (const float*)d_in[13]; const float* brf = (const float*)d_in[14];
    const float* Ro  = (const float*)d_in[15]; const float* bro = (const float*)d_in[16];
    const float* Wl  = (const float*)d_in[17]; const float* bl  = (const float*)d_in[18];
    float* out = (float*)d_out;

    // 1) Input projections -> g_G
    input_gemm<<<dim3(16, 256), 256>>>(x, Wz, Wi, Wf, Wo, bz, bi, bf, bo);

    // 2) Persistent sequential recurrence -> g_Hist (and g_hbuf scratch)
    const size_t smem = (16384 + 8192 + 8448 + 128 + 32) * sizeof(float);
    cudaFuncSetAttribute(recurrence, cudaFuncAttributeMaxDynamicSharedMemorySize, (int)smem);
    recurrence<<<NB, NT, smem>>>(Rz, Ri, Rf, Ro, brz, bri, brf, bro);

    // 3) Output projection -> d_out
    output_gemm<<<dim3(4, 128), 256>>>(Wl, bl, out);
}

// round 8
// speedup vs baseline: 1.6573x; 1.0958x over previous
#include <cuda_runtime.h>
#include <cuda_bf16.h>
#include <cstdint>
#include <cstddef>

// Problem dims (fixed by dataset)
#define BB 32
#define SS 1024
#define II 512
#define HH 512
#define NB 128        // persistent blocks in recurrence
#define NT 128        // threads per recurrence block

// ---------------------------------------------------------------------------
// Scratch (device globals: allocation-free per harness rules)
__device__ float g_G[(size_t)SS * 2048 * BB];          // [s][n][b]
__device__ float g_Hist[(size_t)(SS / 2) * BB * HH];   // [s'][b][h]
__device__ float g_hbuf[2][HH * BB];                   // ping-pong [buf][k][b]
__device__ unsigned g_cnt;
__device__ volatile unsigned g_gen;
// bf16 hi/lo operands for tensor-core input GEMM
__device__ __nv_bfloat16 g_xh[(size_t)SS * BB * II];   // [m=s*32+b][i]
__device__ __nv_bfloat16 g_xl[(size_t)SS * BB * II];
__device__ __nv_bfloat16 g_Wh[2048 * II];              // [n=g*512+h][i]
__device__ __nv_bfloat16 g_Wl[2048 * II];

__device__ __forceinline__ float sigf(float x) { return 1.0f / (1.0f + expf(-x)); }

// Packed fp32x2 helpers (recurrence / output GEMM)
__device__ __forceinline__ void ffma2(unsigned long long& d,
                                      unsigned long long a,
                                      unsigned long long b) {
    asm("fma.rn.f32x2 %0, %1, %2, %0;" : "+l"(d) : "l"(a), "l"(b));
}
__device__ __forceinline__ unsigned long long splat2(float x) {
    unsigned long long r;
    asm("mov.b64 %0, {%1, %1};" : "=l"(r) : "f"(x));
    return r;
}
__device__ __forceinline__ float2 unpack2(unsigned long long v) {
    float2 f;
    asm("mov.b64 {%0, %1}, %2;" : "=f"(f.x), "=f"(f.y) : "l"(v));
    return f;
}

// Base-ISA async-copy + HMMA helpers (compute_100-safe; no tcgen05!)
__device__ __forceinline__ uint32_t smem_u32(const void* p) {
    uint32_t a;
    asm("{ .reg .u64 t; cvta.to.shared.u64 t, %1; cvt.u32.u64 %0, t; }"
        : "=r"(a) : "l"(p));
    return a;
}
__device__ __forceinline__ void cpa16(uint32_t dst, const void* src) {
    asm volatile("cp.async.cg.shared.global [%0], [%1], 16;"
                 :: "r"(dst), "l"(src) : "memory");
}
__device__ __forceinline__ void cpa_commit() {
    asm volatile("cp.async.commit_group;" ::: "memory");
}
__device__ __forceinline__ void cpa_wait0() {
    asm volatile("cp.async.wait_group 0;" ::: "memory");
}
__device__ __forceinline__ void mma_bf16(float* d, const uint32_t* a,
                                         const uint32_t* b) {
    asm volatile(
        "mma.sync.aligned.m16n8k16.row.col.f32.bf16.bf16.f32 "
        "{%0,%1,%2,%3}, {%4,%5,%6,%7}, {%8,%9}, {%0,%1,%2,%3};"
        : "+f"(d[0]), "+f"(d[1]), "+f"(d[2]), "+f"(d[3])
        : "r"(a[0]), "r"(a[1]), "r"(a[2]), "r"(a[3]), "r"(b[0]), "r"(b[1]));
}

// ---------------------------------------------------------------------------
// Prepass: convert x -> g_xh/g_xl ([m=s*32+b][i]) and W -> g_Wh/g_Wl.
__global__ void __launch_bounds__(256) convert_prepass(
    const float* __restrict__ x,
    const float* __restrict__ Wz, const float* __restrict__ Wi,
    const float* __restrict__ Wf, const float* __restrict__ Wo)
{
    const int total = 4194304 + 262144;   // float4 groups
    for (int t = blockIdx.x * blockDim.x + threadIdx.x; t < total;
         t += gridDim.x * blockDim.x) {
        float4 v;
        uint2* oh;
        uint2* ol;
        size_t oidx;
        if (t < 4194304) {                 // x part
            const int b = t >> 17, s = (t >> 7) & 1023, i4 = t & 127;
            v = ((const float4*)x)[(size_t)t];
            const int m = s * 32 + b;
            oidx = (size_t)m * 128 + i4;
            oh = (uint2*)g_xh; ol = (uint2*)g_xl;
        } else {                           // W part
            const int u = t - 4194304;
            const int n = u >> 7, i4 = u & 127;
            const int g = n >> 9, hr = n & 511;
            const float* Wg = (g == 0) ? Wz : (g == 1) ? Wi : (g == 2) ? Wf : Wo;
            v = ((const float4*)Wg)[(size_t)hr * 128 + i4];
            oidx = (size_t)n * 128 + i4;
            oh = (uint2*)g_Wh; ol = (uint2*)g_Wl;
        }
        unsigned short h[4], l[4];
        const float* f = (const float*)&v;
#pragma unroll
        for (int j = 0; j < 4; j++) {
            __nv_bfloat16 bh = __float2bfloat16_rn(f[j]);
            float r = f[j] - __bfloat162float(bh);
            __nv_bfloat16 bl = __float2bfloat16_rn(r);
            h[j] = __bfloat16_as_ushort(bh);
            l[j] = __bfloat16_as_ushort(bl);
        }
        uint2 uh, ul;
        uh.x = (uint32_t)h[0] | ((uint32_t)h[1] << 16);
        uh.y = (uint32_t)h[2] | ((uint32_t)h[3] << 16);
        ul.x = (uint32_t)l[0] | ((uint32_t)l[1] << 16);
        ul.y = (uint32_t)l[2] | ((uint32_t)l[3] << 16);
        oh[oidx] = uh;
        ol[oidx] = ul;
    }
}

// ---------------------------------------------------------------------------
// Tensor-core input GEMM (Ampere-path HMMA): G[m][n] = X[m][:]·W[n][:] + bias
// hi/lo bf16 split, 3 accumulating passes, fp32 register accumulators.
// Block: 256 thr (8 warps), tile 128(m) x 128(n), K=512 in 8 chunks of 64,
// cp.async double-buffered smem staging (pitch 72 bf16 -> conflict-free LDS).
#define IG_PITCH 72
#define IG_ARR   (128 * IG_PITCH)              // bf16 elems per array
#define IG_BUF   (4 * IG_ARR)                  // Ah|Al|Bh|Bl
#define IG_SMEM  (2 * IG_BUF * 2)              // bytes (2 buffers)
__global__ void __launch_bounds__(256, 1) input_gemm_tc(
    const float* __restrict__ bz, const float* __restrict__ bi,
    const float* __restrict__ bf, const float* __restrict__ bo)
{
    extern __shared__ __nv_bfloat16 smb[];
    const uint32_t sb0 = smem_u32(smb);
    const int tid = threadIdx.x;
    const int wid = tid >> 5, lane = tid & 31;
    const int g = lane >> 2, t = lane & 3;
    const int wm = wid >> 2, wn = wid & 3;      // warp tile: 64(m) x 32(n)
    const int bx = blockIdx.x, by = blockIdx.y;
    const int n0 = bx * 128, m0 = by * 128;

    // Stage chunk c (64 k) into buffer buf via cp.async (16 per thread).
    auto stage = [&](int c, int buf) {
        const uint32_t base = sb0 + (uint32_t)buf * (IG_BUF * 2);
        const uint4* srcA_h = (const uint4*)g_xh + (size_t)m0 * 64 + c * 8;
        const uint4* srcA_l = (const uint4*)g_xl + (size_t)m0 * 64 + c * 8;
        const uint4* srcB_h = (const uint4*)g_Wh + (size_t)n0 * 64 + c * 8;
        const uint4* srcB_l = (const uint4*)g_Wl + (size_t)n0 * 64 + c * 8;
        const uint4* srcs[4] = { srcA_h, srcA_l, srcB_h, srcB_l };
#pragma unroll
        for (int a = 0; a < 4; a++) {
#pragma unroll
            for (int i = 0; i < 4; i++) {
                const int idx = i * 256 + tid;       // 1024 uint4 per array
                const int r = idx >> 3, u = idx & 7;
                cpa16(base + (uint32_t)(a * (IG_ARR * 2) + r * (IG_PITCH * 2) + u * 16),
                      srcs[a] + (size_t)r * 64 + u);
            }
        }
        cpa_commit();
    };

    float acc[4][4][4];                          // [mi][ni][reg]
#pragma unroll
    for (int mi = 0; mi < 4; mi++)
#pragma unroll
        for (int ni = 0; ni < 4; ni++)
#pragma unroll
            for (int r = 0; r < 4; r++) acc[mi][ni][r] = 0.0f;

    stage(0, 0);

    for (int c = 0; c < 8; c++) {
        cpa_wait0();
        __syncthreads();
        if (c + 1 < 8) stage(c + 1, (c + 1) & 1);

        const __nv_bfloat16* Ah = smb + (size_t)(c & 1) * IG_BUF;
        const __nv_bfloat16* Al = Ah + IG_ARR;
        const __nv_bfloat16* Bh = Ah + 2 * IG_ARR;
        const __nv_bfloat16* Bl = Ah + 3 * IG_ARR;

#pragma unroll
        for (int ks = 0; ks < 4; ks++) {
            const int k0 = ks * 16;
            uint32_t ah[4][4], al[4][4], bh[4][2], bl[4][2];
#pragma unroll
            for (int mi = 0; mi < 4; mi++) {
                const int r0 = wm * 64 + mi * 16 + g;
                const int cA = k0 + 2 * t;
                ah[mi][0] = *(const uint32_t*)(Ah + r0 * IG_PITCH + cA);
                ah[mi][1] = *(const uint32_t*)(Ah + (r0 + 8) * IG_PITCH + cA);
                ah[mi][2] = *(const uint32_t*)(Ah + r0 * IG_PITCH + cA + 8);
                ah[mi][3] = *(const uint32_t*)(Ah + (r0 + 8) * IG_PITCH + cA + 8);
                al[mi][0] = *(const uint32_t*)(Al + r0 * IG_PITCH + cA);
                al[mi][1] = *(const uint32_t*)(Al + (r0 + 8) * IG_PITCH + cA);
                al[mi][2] = *(const uint32_t*)(Al + r0 * IG_PITCH + cA + 8);
                al[mi][3] = *(const uint32_t*)(Al + (r0 + 8) * IG_PITCH + cA + 8);
            }
#pragma unroll
            for (int ni = 0; ni < 4; ni++) {
                const int rB = wn * 32 + ni * 8 + g;
                const int cB = k0 + 2 * t;
                bh[ni][0] = *(const uint32_t*)(Bh + rB * IG_PITCH + cB);
                bh[ni][1] = *(const uint32_t*)(Bh + rB * IG_PITCH + cB + 8);
                bl[ni][0] = *(const uint32_t*)(Bl + rB * IG_PITCH + cB);
                bl[ni][1] = *(const uint32_t*)(Bl + rB * IG_PITCH + cB + 8);
            }
#pragma unroll
            for (int mi = 0; mi < 4; mi++)
#pragma unroll
                for (int ni = 0; ni < 4; ni++) {
                    mma_bf16(acc[mi][ni], ah[mi], bh[ni]);   // hi*hi
                    mma_bf16(acc[mi][ni], ah[mi], bl[ni]);   // hi*lo
                    mma_bf16(acc[mi][ni], al[mi], bh[ni]);   // lo*hi
                }
        }
        __syncthreads();
    }

    // Epilogue: D[m][n] + bias -> g_G[(s*2048+n)*32 + b], m = s*32+b.
    const int gate = bx >> 2;
    const float* bias = (gate == 0) ? bz : (gate == 1) ? bi : (gate == 2) ? bf : bo;
    const int nlb = (bx & 3) * 128;
#pragma unroll
    for (int mi = 0; mi < 4; mi++) {
        const int row0 = m0 + wm * 64 + mi * 16 + g;
        const int row1 = row0 + 8;
        const int s0 = row0 >> 5, b0 = row0 & 31;
        const int s1 = row1 >> 5, b1 = row1 & 31;
#pragma unroll
        for (int ni = 0; ni < 4; ni++) {
            const int nl = wn * 32 + ni * 8 + 2 * t;
            const int n = n0 + nl;
            const float bv0 = bias[nlb + nl], bv1 = bias[nlb + nl + 1];
            g_G[((size_t)s0 * 2048 + n) * BB + b0]     = acc[mi][ni][0] + bv0;
            g_G[((size_t)s0 * 2048 + n + 1) * BB + b0] = acc[mi][ni][1] + bv1;
            g_G[((size_t)s1 * 2048 + n) * BB + b1]     = acc[mi][ni][2] + bv0;
            g_G[((size_t)s1 * 2048 + n + 1) * BB + b1] = acc[mi][ni][3] + bv1;
        }
    }
}

// ---------------------------------------------------------------------------
// Persistent recurrence. 128 blocks x 128 threads, 1 block/SM. (R6 passing
// version verbatim: FFMA2 core, single-counter generation barrier.)
__global__ void __launch_bounds__(NT, 1) recurrence(
    const float* __restrict__ Rz, const float* __restrict__ Ri,
    const float* __restrict__ Rf, const float* __restrict__ Ro,
    const float* __restrict__ brz, const float* __restrict__ bri,
    const float* __restrict__ brf, const float* __restrict__ bro)
{
    extern __shared__ float sm[];
    float* rs  = sm;                  // [512][32]  R stream     : 16384
    float* hs  = sm + 16384;          // [512][16]  h staged     : 8192
    float* red = sm + 24576;          // [16][16][33] partials   : 8448
    float* csm = red + 8448;          // 128 cell states
    float* brs = csm + 128;           // 32 recurrent biases (p = g*8+c)

    const int tid = threadIdx.x;
    const int bid = blockIdx.x;
    const int jc  = (bid >> 1) * 8;
    const int b0g = (bid & 1) * 16;
    const int w = tid >> 5, l = tid & 31;

    __shared__ unsigned s_base;
    if (tid == 0) s_base = g_gen;     // consistent snapshot (see R1 notes)

    for (int i = 0; i < 32; i++) {
        const int idx = i * 128 + tid;
        const int p = idx & 31, k4 = idx >> 5;
        const int g = p >> 3, c = p & 7;
        const float* Rg = (g == 0) ? Rz : (g == 1) ? Ri : (g == 2) ? Rf : Ro;
        float4 v = *(const float4*)(Rg + (size_t)(jc + c) * HH + k4 * 4);
        rs[(k4 * 4 + 0) * 32 + p] = v.x;
        rs[(k4 * 4 + 1) * 32 + p] = v.y;
        rs[(k4 * 4 + 2) * 32 + p] = v.z;
        rs[(k4 * 4 + 3) * 32 + p] = v.w;
    }
    if (tid < 32) {
        const int g = tid >> 3, c = tid & 7;
        const float* bg = (g == 0) ? brz : (g == 1) ? bri : (g == 2) ? brf : bro;
        brs[tid] = bg[jc + c];
    }
    csm[tid] = 0.0f;
    __syncthreads();
    const unsigned base = s_base;

    const int kg = w * 4 + (l >> 3);
    const int gg = l & 3;
    const int bgp = (l >> 2) & 1;
    const float* rq = rs + (size_t)(kg * 32) * 32 + gg * 8;
    const float* hq = hs + (size_t)(kg * 32) * 16 + bgp * 8;
    const int c_ = tid >> 4;
    const int b_ = tid & 15;

    float gv0 = g_G[(0 * 512 + jc + c_) * BB + b0g + b_];
    float gv1 = g_G[(1 * 512 + jc + c_) * BB + b0g + b_];
    float gv2 = g_G[(2 * 512 + jc + c_) * BB + b0g + b_];
    float gv3 = g_G[(3 * 512 + jc + c_) * BB + b0g + b_];

    for (int s = 0; s < SS; ++s) {
        if (s == 0) {
            const float4 z4 = make_float4(0.f, 0.f, 0.f, 0.f);
#pragma unroll 4
            for (int i = 0; i < 16; i++) {
                const int idx = i * 32 + l;
                const int k = w * 128 + (idx >> 2), x4 = idx & 3;
                *(float4*)&hs[k * 16 + x4 * 4] = z4;
            }
        } else {
            const float* hb = g_hbuf[(s - 1) & 1];
#pragma unroll 4
            for (int i = 0; i < 16; i++) {
                const int idx = i * 32 + l;
                const int k = w * 128 + (idx >> 2), x4 = idx & 3;
                float4 v = __ldcg((const float4*)(hb + k * 32 + b0g + x4 * 4));
                *(float4*)&hs[k * 16 + x4 * 4] = v;
            }
        }
        __syncwarp();

        unsigned long long acc2[8][4];
#pragma unroll
        for (int i = 0; i < 8; i++)
#pragma unroll
            for (int j = 0; j < 4; j++) acc2[i][j] = 0ULL;

        const float* rp = rq;
        const float* hp = hq;
#pragma unroll 4
        for (int kk = 0; kk < 32; kk++) {
            float rr[8];
            *(float4*)(rr)     = *(const float4*)(rp);
            *(float4*)(rr + 4) = *(const float4*)(rp + 4);
            const ulonglong2 h01 = *(const ulonglong2*)(hp);
            const ulonglong2 h23 = *(const ulonglong2*)(hp + 4);
#pragma unroll
            for (int i = 0; i < 8; i++) {
                const unsigned long long a2 = splat2(rr[i]);
                ffma2(acc2[i][0], a2, h01.x);
                ffma2(acc2[i][1], a2, h01.y);
                ffma2(acc2[i][2], a2, h23.x);
                ffma2(acc2[i][3], a2, h23.y);
            }
            rp += 32; hp += 16;
        }

#pragma unroll
        for (int pi = 0; pi < 8; pi++)
#pragma unroll
            for (int bj2 = 0; bj2 < 4; bj2++) {
                const float2 f = unpack2(acc2[pi][bj2]);
                red[(kg * 16 + bgp * 8 + 2 * bj2 + 0) * 33 + gg * 8 + pi] = f.x;
                red[(kg * 16 + bgp * 8 + 2 * bj2 + 1) * 33 + gg * 8 + pi] = f.y;
            }
        __syncthreads();

        float pz = gv0 + brs[0 + c_];
        float pi_ = gv1 + brs[8 + c_];
        float pf = gv2 + brs[16 + c_];
        float po = gv3 + brs[24 + c_];
#pragma unroll
        for (int q = 0; q < 16; q++) {
            const float* rr = red + (q * 16 + b_) * 33 + c_;
            pz  += rr[0];
            pi_ += rr[8];
            pf  += rr[16];
            po  += rr[24];
        }
        const float z  = tanhf(pz);
        const float iv = sigf(pi_);
        const float f  = sigf(pf);
        const float o  = sigf(po);
        const float cc = fmaf(f, csm[tid], z * iv);
        csm[tid] = cc;
        const float h = o * tanhf(cc);
        g_hbuf[s & 1][(jc + c_) * BB + b0g + b_] = h;
        if (s >= SS / 2)
            g_Hist[((size_t)(s - SS / 2) * BB + b0g + b_) * HH + jc + c_] = h;

        if (s < SS - 1) {
            const float* Gn = g_G + (size_t)(s + 1) * (2048 * BB);
            const float t0 = Gn[(0 * 512 + jc + c_) * BB + b0g + b_];
            const float t1 = Gn[(1 * 512 + jc + c_) * BB + b0g + b_];
            const float t2 = Gn[(2 * 512 + jc + c_) * BB + b0g + b_];
            const float t3 = Gn[(3 * 512 + jc + c_) * BB + b0g + b_];

            __threadfence();
            __syncthreads();
            if (tid == 0) {
                const unsigned tgt = base + (unsigned)s + 1u;
                if (atomicAdd(&g_cnt, 1u) == NB - 1u) {
                    atomicExch(&g_cnt, 0u);
                    __threadfence();
                    g_gen = tgt;
                } else {
                    while ((int)(g_gen - tgt) < 0) __nanosleep(32);
                    __threadfence();
                }
            }
            __syncthreads();
            gv0 = t0; gv1 = t1; gv2 = t2; gv3 = t3;
        }
    }
    // Launch-exit state: g_cnt == 0, g_gen == base + SS - 1  (replay-safe).
}

// ---------------------------------------------------------------------------
// Output GEMM: out[b][s'][o] = Hist[s'][b][:] . Wl[o][:] + bl[o]  (fp32)
__global__ void __launch_bounds__(256, 2) output_gemm(
    const float* __restrict__ Wl, const float* __restrict__ bl,
    float* __restrict__ out)
{
    constexpr int BM = 128, BN = 128, BK = 8;
    __shared__ float As[BK][BM + 4];
    __shared__ float Bs[BK][BN + 4];

    const int bx = blockIdx.x;
    const int by = blockIdx.y;
    const int m0 = by * BM;
    const int n0g = bx * BN;

    const int tid  = threadIdx.x;
    const int arow = tid >> 1, acol = (tid & 1) * 4;
    const int brow = tid >> 1, bcol = (tid & 1) * 4;
    const int tx = tid & 15, ty = tid >> 4;

    const float* apk = g_Hist + (size_t)(m0 + arow) * HH + acol;
    const float* bpk = Wl + (size_t)(n0g + brow) * HH + bcol;

    unsigned long long acc2[8][4];
#pragma unroll
    for (int i = 0; i < 8; i++)
#pragma unroll
        for (int j = 0; j < 4; j++) acc2[i][j] = 0ULL;

    float4 av = *(const float4*)(apk);
    float4 bv = *(const float4*)(bpk);

    for (int k0 = 0; k0 < HH; k0 += BK) {
        As[acol + 0][arow] = av.x; As[acol + 1][arow] = av.y;
        As[acol + 2][arow] = av.z; As[acol + 3][arow] = av.w;
        Bs[bcol + 0][brow] = bv.x; Bs[bcol + 1][brow] = bv.y;
        Bs[bcol + 2][brow] = bv.z; Bs[bcol + 3][brow] = bv.w;
        __syncthreads();
        if (k0 + BK < HH) {
            av = *(const float4*)(apk + k0 + BK);
            bv = *(const float4*)(bpk + k0 + BK);
        }
#pragma unroll
        for (int k = 0; k < BK; k++) {
            float ra[8];
            *(float4*)(ra)     = *(const float4*)(&As[k][4 * ty]);
            *(float4*)(ra + 4) = *(const float4*)(&As[k][64 + 4 * ty]);
            const ulonglong2 b01 = *(const ulonglong2*)(&Bs[k][4 * tx]);
            const ulonglong2 b23 = *(const ulonglong2*)(&Bs[k][64 + 4 * tx]);
#pragma unroll
            for (int i = 0; i < 8; i++) {
                const unsigned long long a2 = splat2(ra[i]);
                ffma2(acc2[i][0], a2, b01.x);
                ffma2(acc2[i][1], a2, b01.y);
                ffma2(acc2[i][2], a2, b23.x);
                ffma2(acc2[i][3], a2, b23.y);
            }
        }
        __syncthreads();
    }

    float acc[8][8];
#pragma unroll
    for (int i = 0; i < 8; i++)
#pragma unroll
        for (int jp = 0; jp < 4; jp++) {
            float2 f = unpack2(acc2[i][jp]);
            acc[i][2 * jp] = f.x; acc[i][2 * jp + 1] = f.y;
        }

#pragma unroll
    for (int i = 0; i < 8; i++) {
        const int m = m0 + (i >> 2) * 64 + 4 * ty + (i & 3);
        const int sp = m >> 5, bB = m & 31;
#pragma unroll
        for (int jh = 0; jh < 2; jh++) {
            const int n = n0g + jh * 64 + 4 * tx;
            float4 v = make_float4(acc[i][jh * 4 + 0] + bl[n + 0],
                                   acc[i][jh * 4 + 1] + bl[n + 1],
                                   acc[i][jh * 4 + 2] + bl[n + 2],
                                   acc[i][jh * 4 + 3] + bl[n + 3]);
            *(float4*)(out + ((size_t)bB * (SS / 2) + sp) * II + n) = v;
        }
    }
}

// ---------------------------------------------------------------------------
extern "C" void kernel_launch(void* const* d_in, const int* in_sizes, int n_in,
                              void* d_out, int out_size)
{
    const float* x   = (const float*)d_in[0];
    const float* Wz  = (const float*)d_in[1];  const float* bz  = (const float*)d_in[2];
    const float* Wi  = (const float*)d_in[3];  const float* bi  = (const float*)d_in[4];
    const float* Wf  = (const float*)d_in[5];  const float* bf  = (const float*)d_in[6];
    const float* Wo  = (const float*)d_in[7];  const float* bo  = (const float*)d_in[8];
    const float* Rz  = (const float*)d_in[9];  const float* brz = (const float*)d_in[10];
    const float* Ri  = (const float*)d_in[11]; const float* bri = (const float*)d_in[12];
    const float* Rf  = (const float*)d_in[13]; const float* brf = (const float*)d_in[14];
    const float* Ro  = (const float*)d_in[15]; const float* bro = (const float*)d_in[16];
    const float* Wl  = (const float*)d_in[17]; const float* bl  = (const float*)d_in[18];
    float* out = (float*)d_out;

    // 0) Convert x/W to bf16 hi/lo
    convert_prepass<<<592, 256>>>(x, Wz, Wi, Wf, Wo);

    // 1) Tensor-core (HMMA) input projections -> g_G
    cudaFuncSetAttribute(input_gemm_tc, cudaFuncAttributeMaxDynamicSharedMemorySize, IG_SMEM);
    input_gemm_tc<<<dim3(16, 256), 256, IG_SMEM>>>(bz, bi, bf, bo);

    // 2) Persistent sequential recurrence -> g_Hist
    const size_t smem = (16384 + 8192 + 8448 + 128 + 32) * sizeof(float);
    cudaFuncSetAttribute(recurrence, cudaFuncAttributeMaxDynamicSharedMemorySize, (int)smem);
    recurrence<<<NB, NT, smem>>>(Rz, Ri, Rf, Ro, brz, bri, brf, bro);

    // 3) Output projection -> d_out
    output_gemm<<<dim3(4, 128), 256>>>(Wl, bl, out);
}

// round 9
// speedup vs baseline: 1.9450x; 1.1736x over previous
#include <cuda_runtime.h>
#include <cuda_bf16.h>
#include <cstdint>
#include <cstddef>

// Problem dims (fixed by dataset)
#define BB 32
#define SS 1024
#define II 512
#define HH 512
#define NB 128        // persistent blocks in recurrence
#define NT 128        // threads per recurrence block

// ---------------------------------------------------------------------------
// Scratch (device globals: allocation-free per harness rules)
__device__ float g_G[(size_t)SS * 2048 * BB];          // [s][n][b]
__device__ float g_Hist[(size_t)(SS / 2) * BB * HH];   // [s'][b][h]
__device__ __nv_bfloat16 g_hbf[2][2][BB][HH];          // [buf][hi/lo][b][k]
__device__ unsigned g_cnt;
__device__ volatile unsigned g_gen;
// bf16 hi/lo operands for tensor-core GEMMs
__device__ __nv_bfloat16 g_xh[(size_t)SS * BB * II];   // [m=s*32+b][i]
__device__ __nv_bfloat16 g_xl[(size_t)SS * BB * II];
__device__ __nv_bfloat16 g_Wh[2048 * II];              // [n=g*512+h][i]
__device__ __nv_bfloat16 g_Wl[2048 * II];
__device__ __nv_bfloat16 g_Rh[2048 * HH];              // [n=g*512+h][k]
__device__ __nv_bfloat16 g_Rl[2048 * HH];

__device__ __forceinline__ float sigf(float x) { return 1.0f / (1.0f + expf(-x)); }

// Packed fp32x2 helpers (output GEMM)
__device__ __forceinline__ void ffma2(unsigned long long& d,
                                      unsigned long long a,
                                      unsigned long long b) {
    asm("fma.rn.f32x2 %0, %1, %2, %0;" : "+l"(d) : "l"(a), "l"(b));
}
__device__ __forceinline__ unsigned long long splat2(float x) {
    unsigned long long r;
    asm("mov.b64 %0, {%1, %1};" : "=l"(r) : "f"(x));
    return r;
}
__device__ __forceinline__ float2 unpack2(unsigned long long v) {
    float2 f;
    asm("mov.b64 {%0, %1}, %2;" : "=f"(f.x), "=f"(f.y) : "l"(v));
    return f;
}

// Base-ISA async-copy + HMMA + ldmatrix helpers (compute_100-safe)
__device__ __forceinline__ uint32_t smem_u32(const void* p) {
    uint32_t a;
    asm("{ .reg .u64 t; cvta.to.shared.u64 t, %1; cvt.u32.u64 %0, t; }"
        : "=r"(a) : "l"(p));
    return a;
}
__device__ __forceinline__ void cpa16(uint32_t dst, const void* src) {
    asm volatile("cp.async.cg.shared.global [%0], [%1], 16;"
                 :: "r"(dst), "l"(src) : "memory");
}
__device__ __forceinline__ void cpa_commit() {
    asm volatile("cp.async.commit_group;" ::: "memory");
}
__device__ __forceinline__ void cpa_wait0() {
    asm volatile("cp.async.wait_group 0;" ::: "memory");
}
__device__ __forceinline__ void mma_bf16(float* d, const uint32_t* a,
                                         const uint32_t* b) {
    asm volatile(
        "mma.sync.aligned.m16n8k16.row.col.f32.bf16.bf16.f32 "
        "{%0,%1,%2,%3}, {%4,%5,%6,%7}, {%8,%9}, {%0,%1,%2,%3};"
        : "+f"(d[0]), "+f"(d[1]), "+f"(d[2]), "+f"(d[3])
        : "r"(a[0]), "r"(a[1]), "r"(a[2]), "r"(a[3]), "r"(b[0]), "r"(b[1]));
}
__device__ __forceinline__ void ldsm4(uint32_t* r, uint32_t addr) {
    asm volatile("ldmatrix.sync.aligned.m8n8.x4.shared.b16 {%0,%1,%2,%3}, [%4];"
                 : "=r"(r[0]), "=r"(r[1]), "=r"(r[2]), "=r"(r[3]) : "r"(addr));
}

// ---------------------------------------------------------------------------
// Prepass: x -> g_xh/g_xl ([m][i]),  W -> g_Wh/g_Wl,  R -> g_Rh/g_Rl.
__global__ void __launch_bounds__(256) convert_prepass(
    const float* __restrict__ x,
    const float* __restrict__ Wz, const float* __restrict__ Wi,
    const float* __restrict__ Wf, const float* __restrict__ Wo,
    const float* __restrict__ Rz, const float* __restrict__ Ri,
    const float* __restrict__ Rf, const float* __restrict__ Ro)
{
    const int total = 4194304 + 262144 + 262144;   // float4 groups
    for (int t = blockIdx.x * blockDim.x + threadIdx.x; t < total;
         t += gridDim.x * blockDim.x) {
        float4 v;
        uint2* oh;
        uint2* ol;
        size_t oidx;
        if (t < 4194304) {                 // x part
            const int b = t >> 17, s = (t >> 7) & 1023, i4 = t & 127;
            v = ((const float4*)x)[(size_t)t];
            const int m = s * 32 + b;
            oidx = (size_t)m * 128 + i4;
            oh = (uint2*)g_xh; ol = (uint2*)g_xl;
        } else if (t < 4194304 + 262144) { // W part
            const int u = t - 4194304;
            const int n = u >> 7, i4 = u & 127;
            const int g = n >> 9, hr = n & 511;
            const float* Wg = (g == 0) ? Wz : (g == 1) ? Wi : (g == 2) ? Wf : Wo;
            v = ((const float4*)Wg)[(size_t)hr * 128 + i4];
            oidx = (size_t)n * 128 + i4;
            oh = (uint2*)g_Wh; ol = (uint2*)g_Wl;
        } else {                           // R part
            const int u = t - 4194304 - 262144;
            const int n = u >> 7, i4 = u & 127;
            const int g = n >> 9, hr = n & 511;
            const float* Rg = (g == 0) ? Rz : (g == 1) ? Ri : (g == 2) ? Rf : Ro;
            v = ((const float4*)Rg)[(size_t)hr * 128 + i4];
            oidx = (size_t)n * 128 + i4;
            oh = (uint2*)g_Rh; ol = (uint2*)g_Rl;
        }
        unsigned short h[4], l[4];
        const float* f = (const float*)&v;
#pragma unroll
        for (int j = 0; j < 4; j++) {
            __nv_bfloat16 bh = __float2bfloat16_rn(f[j]);
            float r = f[j] - __bfloat162float(bh);
            __nv_bfloat16 bl = __float2bfloat16_rn(r);
            h[j] = __bfloat16_as_ushort(bh);
            l[j] = __bfloat16_as_ushort(bl);
        }
        uint2 uh, ul;
        uh.x = (uint32_t)h[0] | ((uint32_t)h[1] << 16);
        uh.y = (uint32_t)h[2] | ((uint32_t)h[3] << 16);
        ul.x = (uint32_t)l[0] | ((uint32_t)l[1] << 16);
        ul.y = (uint32_t)l[2] | ((uint32_t)l[3] << 16);
        oh[oidx] = uh;
        ol[oidx] = ul;
    }
}

// ---------------------------------------------------------------------------
// Tensor-core input GEMM (HMMA, unchanged from R8 pass): G = X·W^T + bias.
#define IG_PITCH 72
#define IG_ARR   (128 * IG_PITCH)
#define IG_BUF   (4 * IG_ARR)
#define IG_SMEM  (2 * IG_BUF * 2)
__global__ void __launch_bounds__(256, 1) input_gemm_tc(
    const float* __restrict__ bz, const float* __restrict__ bi,
    const float* __restrict__ bf, const float* __restrict__ bo)
{
    extern __shared__ __nv_bfloat16 smb[];
    const uint32_t sb0 = smem_u32(smb);
    const int tid = threadIdx.x;
    const int wid = tid >> 5, lane = tid & 31;
    const int g = lane >> 2, t = lane & 3;
    const int wm = wid >> 2, wn = wid & 3;
    const int bx = blockIdx.x, by = blockIdx.y;
    const int n0 = bx * 128, m0 = by * 128;

    auto stage = [&](int c, int buf) {
        const uint32_t base = sb0 + (uint32_t)buf * (IG_BUF * 2);
        const uint4* srcA_h = (const uint4*)g_xh + (size_t)m0 * 64 + c * 8;
        const uint4* srcA_l = (const uint4*)g_xl + (size_t)m0 * 64 + c * 8;
        const uint4* srcB_h = (const uint4*)g_Wh + (size_t)n0 * 64 + c * 8;
        const uint4* srcB_l = (const uint4*)g_Wl + (size_t)n0 * 64 + c * 8;
        const uint4* srcs[4] = { srcA_h, srcA_l, srcB_h, srcB_l };
#pragma unroll
        for (int a = 0; a < 4; a++) {
#pragma unroll
            for (int i = 0; i < 4; i++) {
                const int idx = i * 256 + tid;
                const int r = idx >> 3, u = idx & 7;
                cpa16(base + (uint32_t)(a * (IG_ARR * 2) + r * (IG_PITCH * 2) + u * 16),
                      srcs[a] + (size_t)r * 64 + u);
            }
        }
        cpa_commit();
    };

    float acc[4][4][4];
#pragma unroll
    for (int mi = 0; mi < 4; mi++)
#pragma unroll
        for (int ni = 0; ni < 4; ni++)
#pragma unroll
            for (int r = 0; r < 4; r++) acc[mi][ni][r] = 0.0f;

    stage(0, 0);

    for (int c = 0; c < 8; c++) {
        cpa_wait0();
        __syncthreads();
        if (c + 1 < 8) stage(c + 1, (c + 1) & 1);

        const __nv_bfloat16* Ah = smb + (size_t)(c & 1) * IG_BUF;
        const __nv_bfloat16* Al = Ah + IG_ARR;
        const __nv_bfloat16* Bh = Ah + 2 * IG_ARR;
        const __nv_bfloat16* Bl = Ah + 3 * IG_ARR;

#pragma unroll
        for (int ks = 0; ks < 4; ks++) {
            const int k0 = ks * 16;
            uint32_t ah[4][4], al[4][4], bh[4][2], bl[4][2];
#pragma unroll
            for (int mi = 0; mi < 4; mi++) {
                const int r0 = wm * 64 + mi * 16 + g;
                const int cA = k0 + 2 * t;
                ah[mi][0] = *(const uint32_t*)(Ah + r0 * IG_PITCH + cA);
                ah[mi][1] = *(const uint32_t*)(Ah + (r0 + 8) * IG_PITCH + cA);
                ah[mi][2] = *(const uint32_t*)(Ah + r0 * IG_PITCH + cA + 8);
                ah[mi][3] = *(const uint32_t*)(Ah + (r0 + 8) * IG_PITCH + cA + 8);
                al[mi][0] = *(const uint32_t*)(Al + r0 * IG_PITCH + cA);
                al[mi][1] = *(const uint32_t*)(Al + (r0 + 8) * IG_PITCH + cA);
                al[mi][2] = *(const uint32_t*)(Al + r0 * IG_PITCH + cA + 8);
                al[mi][3] = *(const uint32_t*)(Al + (r0 + 8) * IG_PITCH + cA + 8);
            }
#pragma unroll
            for (int ni = 0; ni < 4; ni++) {
                const int rB = wn * 32 + ni * 8 + g;
                const int cB = k0 + 2 * t;
                bh[ni][0] = *(const uint32_t*)(Bh + rB * IG_PITCH + cB);
                bh[ni][1] = *(const uint32_t*)(Bh + rB * IG_PITCH + cB + 8);
                bl[ni][0] = *(const uint32_t*)(Bl + rB * IG_PITCH + cB);
                bl[ni][1] = *(const uint32_t*)(Bl + rB * IG_PITCH + cB + 8);
            }
#pragma unroll
            for (int mi = 0; mi < 4; mi++)
#pragma unroll
                for (int ni = 0; ni < 4; ni++) {
                    mma_bf16(acc[mi][ni], ah[mi], bh[ni]);
                    mma_bf16(acc[mi][ni], ah[mi], bl[ni]);
                    mma_bf16(acc[mi][ni], al[mi], bh[ni]);
                }
        }
        __syncthreads();
    }

    const int gate = bx >> 2;
    const float* bias = (gate == 0) ? bz : (gate == 1) ? bi : (gate == 2) ? bf : bo;
    const int nlb = (bx & 3) * 128;
#pragma unroll
    for (int mi = 0; mi < 4; mi++) {
        const int row0 = m0 + wm * 64 + mi * 16 + g;
        const int row1 = row0 + 8;
        const int s0 = row0 >> 5, b0 = row0 & 31;
        const int s1 = row1 >> 5, b1 = row1 & 31;
#pragma unroll
        for (int ni = 0; ni < 4; ni++) {
            const int nl = wn * 32 + ni * 8 + 2 * t;
            const int n = n0 + nl;
            const float bv0 = bias[nlb + nl], bv1 = bias[nlb + nl + 1];
            g_G[((size_t)s0 * 2048 + n) * BB + b0]     = acc[mi][ni][0] + bv0;
            g_G[((size_t)s0 * 2048 + n + 1) * BB + b0] = acc[mi][ni][1] + bv1;
            g_G[((size_t)s1 * 2048 + n) * BB + b1]     = acc[mi][ni][2] + bv0;
            g_G[((size_t)s1 * 2048 + n + 1) * BB + b1] = acc[mi][ni][3] + bv1;
        }
    }
}

// ---------------------------------------------------------------------------
// Tensor-core persistent recurrence. 128 blocks x 128 threads, 1 block/SM.
// Block = (n-group j = bid>>1 -> hcols jc=8j, b-half b0g=(bid&1)*16).
// Per step: pre[32 n][16 b] = G + R·h via mma.sync bf16 hi/lo (3 passes),
// 4 warps k-split x128, smem reduce, gate math, h emitted as bf16 hi/lo.
// smem (bf16 elems): Rs hi 0, lo 16640; hs hi 33280, lo 41600; total 49920.
#define RS_H 0
#define RS_L 16640
#define HS_H 33280
#define HS_L 41600
#define RC_PITCH 520
#define RC_SMEM (49920 * 2 + (2304 + 128 + 32) * 4)   // 109,696 B
__global__ void __launch_bounds__(NT, 1) recurrence(
    const float* __restrict__ brz, const float* __restrict__ bri,
    const float* __restrict__ brf, const float* __restrict__ bro)
{
    extern __shared__ __nv_bfloat16 smb[];
    float* red = (float*)(smb + 49920);   // [4][32][18]
    float* csm = red + 2304;              // 128 cell states
    float* brs = csm + 128;               // 32 biases (p = g*8+c)
    const uint32_t sbb = smem_u32(smb);

    const int tid = threadIdx.x;
    const int bid = blockIdx.x;
    const int jc  = (bid >> 1) * 8;
    const int b0g = (bid & 1) * 16;
    const int w = tid >> 5, lane = tid & 31;

    __shared__ unsigned s_base;
    if (tid == 0) s_base = g_gen;     // consistent snapshot (see R1 notes)

    // Stage R (32 rows m=g*8+c -> global n=g*512+jc+c), hi+lo, pitch 520.
    for (int i = 0; i < 32; i++) {
        const int idx = i * 128 + tid;            // 4096 uint4 total
        const int part = idx >> 11, rest = idx & 2047;
        const int m = rest >> 6, u = rest & 63;
        const int n = (m >> 3) * 512 + jc + (m & 7);
        const uint4 v = *((const uint4*)(part ? g_Rl : g_Rh) + (size_t)n * 64 + u);
        *(uint4*)(smb + (part ? RS_L : RS_H) + m * RC_PITCH + u * 8) = v;
    }
    if (tid < 32) {
        const int g = tid >> 3, c = tid & 7;
        const float* bg = (g == 0) ? brz : (g == 1) ? bri : (g == 2) ? brf : bro;
        brs[tid] = bg[jc + c];
    }
    csm[tid] = 0.0f;
    __syncthreads();
    const unsigned base = s_base;

    // ldmatrix lane-address components
    const int arow = (lane & 15) * RC_PITCH;          // A: rows m (tile pairs)
    const int akad = (lane >> 4) << 3;                // A: +8 k for tiles 2,3
    const int brow = (((lane >> 4) & 1) * 8 + (lane & 7)) * RC_PITCH;  // B rows n
    const int bkad = ((lane >> 3) & 1) * 8;           // B: +8 k for odd tiles
    // cell roles
    const int c_ = tid >> 4;          // hcol 0..7
    const int b_ = tid & 15;          // batch 0..15
    const int grp = lane >> 2, qp = lane & 3;

    // G prefetch for s = 0
    float gv0 = g_G[(0 * 512 + jc + c_) * BB + b0g + b_];
    float gv1 = g_G[(1 * 512 + jc + c_) * BB + b0g + b_];
    float gv2 = g_G[(2 * 512 + jc + c_) * BB + b0g + b_];
    float gv3 = g_G[(3 * 512 + jc + c_) * BB + b0g + b_];

    for (int s = 0; s < SS; ++s) {
        // Stage h (bf16 hi/lo, 16 b-rows x 512 k, pitch 520).
        if (s == 0) {
            const uint4 z4 = make_uint4(0, 0, 0, 0);
#pragma unroll 4
            for (int i = 0; i < 16; i++) {
                const int idx = i * 128 + tid;        // 2048 uint4
                const int part = idx >> 10, rest = idx & 1023;
                const int r = rest >> 6, u = rest & 63;
                *(uint4*)(smb + (part ? HS_L : HS_H) + r * RC_PITCH + u * 8) = z4;
            }
        } else {
            const int pb = (s - 1) & 1;
            const uint4* hsrc = (const uint4*)g_hbf;
#pragma unroll 4
            for (int i = 0; i < 16; i++) {
                const int idx = i * 128 + tid;
                const int part = idx >> 10, rest = idx & 1023;
                const int r = rest >> 6, u = rest & 63;
                const uint4 v = __ldcg(hsrc + ((size_t)((pb * 2 + part) * 32 + b0g + r)) * 64 + u);
                *(uint4*)(smb + (part ? HS_L : HS_H) + r * RC_PITCH + u * 8) = v;
            }
        }
        __syncthreads();

        // MMA: warp w covers k in [w*128, w*128+128), 8 k-steps of 16.
        float acc[2][2][4];
#pragma unroll
        for (int mi = 0; mi < 2; mi++)
#pragma unroll
            for (int ni = 0; ni < 2; ni++)
#pragma unroll
                for (int r = 0; r < 4; r++) acc[mi][ni][r] = 0.0f;

#pragma unroll
        for (int ks = 0; ks < 8; ks++) {
            const int kb = w * 128 + ks * 16;
            uint32_t Ah0[4], Ah1[4], Al0[4], Al1[4], Bh[4], Bl[4];
            ldsm4(Ah0, sbb + 2 * (RS_H + arow + kb + akad));
            ldsm4(Ah1, sbb + 2 * (RS_H + 16 * RC_PITCH + arow + kb + akad));
            ldsm4(Al0, sbb + 2 * (RS_L + arow + kb + akad));
            ldsm4(Al1, sbb + 2 * (RS_L + 16 * RC_PITCH + arow + kb + akad));
            ldsm4(Bh,  sbb + 2 * (HS_H + brow + kb + bkad));
            ldsm4(Bl,  sbb + 2 * (HS_L + brow + kb + bkad));
            mma_bf16(acc[0][0], Ah0, Bh);     mma_bf16(acc[0][1], Ah0, Bh + 2);
            mma_bf16(acc[1][0], Ah1, Bh);     mma_bf16(acc[1][1], Ah1, Bh + 2);
            mma_bf16(acc[0][0], Ah0, Bl);     mma_bf16(acc[0][1], Ah0, Bl + 2);
            mma_bf16(acc[1][0], Ah1, Bl);     mma_bf16(acc[1][1], Ah1, Bl + 2);
            mma_bf16(acc[0][0], Al0, Bh);     mma_bf16(acc[0][1], Al0, Bh + 2);
            mma_bf16(acc[1][0], Al1, Bh);     mma_bf16(acc[1][1], Al1, Bh + 2);
        }

        // Partials -> red[w][n=0..31][b=0..15] pitch 18
#pragma unroll
        for (int mi = 0; mi < 2; mi++)
#pragma unroll
            for (int ni = 0; ni < 2; ni++) {
                const int row = mi * 16 + grp;
                const int col = ni * 8 + qp * 2;
                *(float2*)&red[(w * 32 + row) * 18 + col] =
                    make_float2(acc[mi][ni][0], acc[mi][ni][1]);
                *(float2*)&red[(w * 32 + row + 8) * 18 + col] =
                    make_float2(acc[mi][ni][2], acc[mi][ni][3]);
            }
        __syncthreads();

        // Gate phase: cell (hcol c_, batch b_); local n-row = g*8 + c_.
        float pz = gv0 + brs[0 + c_];
        float pi_ = gv1 + brs[8 + c_];
        float pf = gv2 + brs[16 + c_];
        float po = gv3 + brs[24 + c_];
#pragma unroll
        for (int q = 0; q < 4; q++) {
            pz  += red[(q * 32 + 0 + c_) * 18 + b_];
            pi_ += red[(q * 32 + 8 + c_) * 18 + b_];
            pf  += red[(q * 32 + 16 + c_) * 18 + b_];
            po  += red[(q * 32 + 24 + c_) * 18 + b_];
        }
        const float z  = tanhf(pz);
        const float iv = sigf(pi_);
        const float f  = sigf(pf);
        const float o  = sigf(po);
        const float cc = fmaf(f, csm[tid], z * iv);
        csm[tid] = cc;
        const float h = o * tanhf(cc);
        // Emit h as bf16 hi/lo to [buf][part][b][k]
        {
            const __nv_bfloat16 hh = __float2bfloat16_rn(h);
            const __nv_bfloat16 hl = __float2bfloat16_rn(h - __bfloat162float(hh));
            g_hbf[s & 1][0][b0g + b_][jc + c_] = hh;
            g_hbf[s & 1][1][b0g + b_][jc + c_] = hl;
        }
        if (s >= SS / 2)
            g_Hist[((size_t)(s - SS / 2) * BB + b0g + b_) * HH + jc + c_] = h;

        // Prefetch next step's G, then grid barrier (latency overlaps spin).
        if (s < SS - 1) {
            const float* Gn = g_G + (size_t)(s + 1) * (2048 * BB);
            const float t0 = Gn[(0 * 512 + jc + c_) * BB + b0g + b_];
            const float t1 = Gn[(1 * 512 + jc + c_) * BB + b0g + b_];
            const float t2 = Gn[(2 * 512 + jc + c_) * BB + b0g + b_];
            const float t3 = Gn[(3 * 512 + jc + c_) * BB + b0g + b_];

            __threadfence();
            __syncthreads();
            if (tid == 0) {
                const unsigned tgt = base + (unsigned)s + 1u;
                if (atomicAdd(&g_cnt, 1u) == NB - 1u) {
                    atomicExch(&g_cnt, 0u);
                    __threadfence();
                    g_gen = tgt;
                } else {
                    while ((int)(g_gen - tgt) < 0) __nanosleep(32);
                    __threadfence();
                }
            }
            __syncthreads();
            gv0 = t0; gv1 = t1; gv2 = t2; gv3 = t3;
        }
    }
    // Launch-exit state: g_cnt == 0, g_gen == base + SS - 1  (replay-safe).
}

// ---------------------------------------------------------------------------
// Output GEMM: out[b][s'][o] = Hist[s'][b][:] . Wl[o][:] + bl[o]  (fp32)
__global__ void __launch_bounds__(256, 2) output_gemm(
    const float* __restrict__ Wl, const float* __restrict__ bl,
    float* __restrict__ out)
{
    constexpr int BM = 128, BN = 128, BK = 8;
    __shared__ float As[BK][BM + 4];
    __shared__ float Bs[BK][BN + 4];

    const int bx = blockIdx.x;
    const int by = blockIdx.y;
    const int m0 = by * BM;
    const int n0g = bx * BN;

    const int tid  = threadIdx.x;
    const int arow = tid >> 1, acol = (tid & 1) * 4;
    const int brow = tid >> 1, bcol = (tid & 1) * 4;
    const int tx = tid & 15, ty = tid >> 4;

    const float* apk = g_Hist + (size_t)(m0 + arow) * HH + acol;
    const float* bpk = Wl + (size_t)(n0g + brow) * HH + bcol;

    unsigned long long acc2[8][4];
#pragma unroll
    for (int i = 0; i < 8; i++)
#pragma unroll
        for (int j = 0; j < 4; j++) acc2[i][j] = 0ULL;

    float4 av = *(const float4*)(apk);
    float4 bv = *(const float4*)(bpk);

    for (int k0 = 0; k0 < HH; k0 += BK) {
        As[acol + 0][arow] = av.x; As[acol + 1][arow] = av.y;
        As[acol + 2][arow] = av.z; As[acol + 3][arow] = av.w;
        Bs[bcol + 0][brow] = bv.x; Bs[bcol + 1][brow] = bv.y;
        Bs[bcol + 2][brow] = bv.z; Bs[bcol + 3][brow] = bv.w;
        __syncthreads();
        if (k0 + BK < HH) {
            av = *(const float4*)(apk + k0 + BK);
            bv = *(const float4*)(bpk + k0 + BK);
        }
#pragma unroll
        for (int k = 0; k < BK; k++) {
            float ra[8];
            *(float4*)(ra)     = *(const float4*)(&As[k][4 * ty]);
            *(float4*)(ra + 4) = *(const float4*)(&As[k][64 + 4 * ty]);
            const ulonglong2 b01 = *(const ulonglong2*)(&Bs[k][4 * tx]);
            const ulonglong2 b23 = *(const ulonglong2*)(&Bs[k][64 + 4 * tx]);
#pragma unroll
            for (int i = 0; i < 8; i++) {
                const unsigned long long a2 = splat2(ra[i]);
                ffma2(acc2[i][0], a2, b01.x);
                ffma2(acc2[i][1], a2, b01.y);
                ffma2(acc2[i][2], a2, b23.x);
                ffma2(acc2[i][3], a2, b23.y);
            }
        }
        __syncthreads();
    }

    float acc[8][8];
#pragma unroll
    for (int i = 0; i < 8; i++)
#pragma unroll
        for (int jp = 0; jp < 4; jp++) {
            float2 f = unpack2(acc2[i][jp]);
            acc[i][2 * jp] = f.x; acc[i][2 * jp + 1] = f.y;
        }

#pragma unroll
    for (int i = 0; i < 8; i++) {
        const int m = m0 + (i >> 2) * 64 + 4 * ty + (i & 3);
        const int sp = m >> 5, bB = m & 31;
#pragma unroll
        for (int jh = 0; jh < 2; jh++) {
            const int n = n0g + jh * 64 + 4 * tx;
            float4 v = make_float4(acc[i][jh * 4 + 0] + bl[n + 0],
                                   acc[i][jh * 4 + 1] + bl[n + 1],
                                   acc[i][jh * 4 + 2] + bl[n + 2],
                                   acc[i][jh * 4 + 3] + bl[n + 3]);
            *(float4*)(out + ((size_t)bB * (SS / 2) + sp) * II + n) = v;
        }
    }
}

// ---------------------------------------------------------------------------
extern "C" void kernel_launch(void* const* d_in, const int* in_sizes, int n_in,
                              void* d_out, int out_size)
{
    const float* x   = (const float*)d_in[0];
    const float* Wz  = (const float*)d_in[1];  const float* bz  = (const float*)d_in[2];
    const float* Wi  = (const float*)d_in[3];  const float* bi  = (const float*)d_in[4];
    const float* Wf  = (const float*)d_in[5];  const float* bf  = (const float*)d_in[6];
    const float* Wo  = (const float*)d_in[7];  const float* bo  = (const float*)d_in[8];
    const float* Rz  = (const float*)d_in[9];  const float* brz = (const float*)d_in[10];
    const float* Ri  = (const float*)d_in[11]; const float* bri = (const float*)d_in[12];
    const float* Rf  = (const float*)d_in[13]; const float* brf = (const float*)d_in[14];
    const float* Ro  = (const float*)d_in[15]; const float* bro = (const float*)d_in[16];
    const float* Wl  = (const float*)d_in[17]; const float* bl  = (const float*)d_in[18];
    float* out = (float*)d_out;

    // 0) Convert x/W/R to bf16 hi/lo
    convert_prepass<<<592, 256>>>(x, Wz, Wi, Wf, Wo, Rz, Ri, Rf, Ro);

    // 1) Tensor-core (HMMA) input projections -> g_G
    cudaFuncSetAttribute(input_gemm_tc, cudaFuncAttributeMaxDynamicSharedMemorySize, IG_SMEM);
    input_gemm_tc<<<dim3(16, 256), 256, IG_SMEM>>>(bz, bi, bf, bo);

    // 2) Tensor-core persistent recurrence -> g_Hist
    cudaFuncSetAttribute(recurrence, cudaFuncAttributeMaxDynamicSharedMemorySize, RC_SMEM);
    recurrence<<<NB, NT, RC_SMEM>>>(brz, bri, brf, bro);

    // 3) Output projection -> d_out
    output_gemm<<<dim3(4, 128), 256>>>(Wl, bl, out);
}

// round 10
// speedup vs baseline: 1.9848x; 1.0204x over previous
#include <cuda_runtime.h>
#include <cuda_bf16.h>
#include <cstdint>
#include <cstddef>

// Problem dims (fixed by dataset)
#define BB 32
#define SS 1024
#define II 512
#define HH 512
#define NB 128        // persistent blocks in recurrence
#define NT 256        // threads per recurrence block (8 warps)

// ---------------------------------------------------------------------------
// Scratch (device globals: allocation-free per harness rules)
__device__ float g_G[(size_t)SS * 2048 * BB];          // [s][n][b]
__device__ float g_Hist[(size_t)(SS / 2) * BB * HH];   // [s'][b][h]
__device__ __nv_bfloat16 g_hbf[2][2][BB][HH];          // [buf][hi/lo][b][k]
__device__ unsigned g_cnt;
__device__ volatile unsigned g_gen;
// bf16 hi/lo operands for tensor-core GEMMs
__device__ __nv_bfloat16 g_xh[(size_t)SS * BB * II];   // [m=s*32+b][i]
__device__ __nv_bfloat16 g_xl[(size_t)SS * BB * II];
__device__ __nv_bfloat16 g_Wh[2048 * II];              // [n=g*512+h][i]
__device__ __nv_bfloat16 g_Wl[2048 * II];
__device__ __nv_bfloat16 g_Rh[2048 * HH];              // [n=g*512+h][k]
__device__ __nv_bfloat16 g_Rl[2048 * HH];

__device__ __forceinline__ float sigf(float x) { return 1.0f / (1.0f + expf(-x)); }

// Packed fp32x2 helpers (output GEMM)
__device__ __forceinline__ void ffma2(unsigned long long& d,
                                      unsigned long long a,
                                      unsigned long long b) {
    asm("fma.rn.f32x2 %0, %1, %2, %0;" : "+l"(d) : "l"(a), "l"(b));
}
__device__ __forceinline__ unsigned long long splat2(float x) {
    unsigned long long r;
    asm("mov.b64 %0, {%1, %1};" : "=l"(r) : "f"(x));
    return r;
}
__device__ __forceinline__ float2 unpack2(unsigned long long v) {
    float2 f;
    asm("mov.b64 {%0, %1}, %2;" : "=f"(f.x), "=f"(f.y) : "l"(v));
    return f;
}

// Base-ISA async-copy + HMMA + ldmatrix helpers (compute_100-safe)
__device__ __forceinline__ uint32_t smem_u32(const void* p) {
    uint32_t a;
    asm("{ .reg .u64 t; cvta.to.shared.u64 t, %1; cvt.u32.u64 %0, t; }"
        : "=r"(a) : "l"(p));
    return a;
}
__device__ __forceinline__ void cpa16(uint32_t dst, const void* src) {
    asm volatile("cp.async.cg.shared.global [%0], [%1], 16;"
                 :: "r"(dst), "l"(src) : "memory");
}
__device__ __forceinline__ void cpa_commit() {
    asm volatile("cp.async.commit_group;" ::: "memory");
}
__device__ __forceinline__ void cpa_wait0() {
    asm volatile("cp.async.wait_group 0;" ::: "memory");
}
__device__ __forceinline__ void mma_bf16(float* d, const uint32_t* a,
                                         const uint32_t* b) {
    asm volatile(
        "mma.sync.aligned.m16n8k16.row.col.f32.bf16.bf16.f32 "
        "{%0,%1,%2,%3}, {%4,%5,%6,%7}, {%8,%9}, {%0,%1,%2,%3};"
        : "+f"(d[0]), "+f"(d[1]), "+f"(d[2]), "+f"(d[3])
        : "r"(a[0]), "r"(a[1]), "r"(a[2]), "r"(a[3]), "r"(b[0]), "r"(b[1]));
}
__device__ __forceinline__ void ldsm4(uint32_t* r, uint32_t addr) {
    asm volatile("ldmatrix.sync.aligned.m8n8.x4.shared.b16 {%0,%1,%2,%3}, [%4];"
                 : "=r"(r[0]), "=r"(r[1]), "=r"(r[2]), "=r"(r[3]) : "r"(addr));
}

// ---------------------------------------------------------------------------
// Prepass: x -> g_xh/g_xl ([m][i]),  W -> g_Wh/g_Wl,  R -> g_Rh/g_Rl.
__global__ void __launch_bounds__(256) convert_prepass(
    const float* __restrict__ x,
    const float* __restrict__ Wz, const float* __restrict__ Wi,
    const float* __restrict__ Wf, const float* __restrict__ Wo,
    const float* __restrict__ Rz, const float* __restrict__ Ri,
    const float* __restrict__ Rf, const float* __restrict__ Ro)
{
    const int total = 4194304 + 262144 + 262144;   // float4 groups
    for (int t = blockIdx.x * blockDim.x + threadIdx.x; t < total;
         t += gridDim.x * blockDim.x) {
        float4 v;
        uint2* oh;
        uint2* ol;
        size_t oidx;
        if (t < 4194304) {                 // x part
            const int b = t >> 17, s = (t >> 7) & 1023, i4 = t & 127;
            v = ((const float4*)x)[(size_t)t];
            const int m = s * 32 + b;
            oidx = (size_t)m * 128 + i4;
            oh = (uint2*)g_xh; ol = (uint2*)g_xl;
        } else if (t < 4194304 + 262144) { // W part
            const int u = t - 4194304;
            const int n = u >> 7, i4 = u & 127;
            const int g = n >> 9, hr = n & 511;
            const float* Wg = (g == 0) ? Wz : (g == 1) ? Wi : (g == 2) ? Wf : Wo;
            v = ((const float4*)Wg)[(size_t)hr * 128 + i4];
            oidx = (size_t)n * 128 + i4;
            oh = (uint2*)g_Wh; ol = (uint2*)g_Wl;
        } else {                           // R part
            const int u = t - 4194304 - 262144;
            const int n = u >> 7, i4 = u & 127;
            const int g = n >> 9, hr = n & 511;
            const float* Rg = (g == 0) ? Rz : (g == 1) ? Ri : (g == 2) ? Rf : Ro;
            v = ((const float4*)Rg)[(size_t)hr * 128 + i4];
            oidx = (size_t)n * 128 + i4;
            oh = (uint2*)g_Rh; ol = (uint2*)g_Rl;
        }
        unsigned short h[4], l[4];
        const float* f = (const float*)&v;
#pragma unroll
        for (int j = 0; j < 4; j++) {
            __nv_bfloat16 bh = __float2bfloat16_rn(f[j]);
            float r = f[j] - __bfloat162float(bh);
            __nv_bfloat16 bl = __float2bfloat16_rn(r);
            h[j] = __bfloat16_as_ushort(bh);
            l[j] = __bfloat16_as_ushort(bl);
        }
        uint2 uh, ul;
        uh.x = (uint32_t)h[0] | ((uint32_t)h[1] << 16);
        uh.y = (uint32_t)h[2] | ((uint32_t)h[3] << 16);
        ul.x = (uint32_t)l[0] | ((uint32_t)l[1] << 16);
        ul.y = (uint32_t)l[2] | ((uint32_t)l[3] << 16);
        oh[oidx] = uh;
        ol[oidx] = ul;
    }
}

// ---------------------------------------------------------------------------
// Tensor-core input GEMM (HMMA, unchanged from R9 pass): G = X·W^T + bias.
#define IG_PITCH 72
#define IG_ARR   (128 * IG_PITCH)
#define IG_BUF   (4 * IG_ARR)
#define IG_SMEM  (2 * IG_BUF * 2)
__global__ void __launch_bounds__(256, 1) input_gemm_tc(
    const float* __restrict__ bz, const float* __restrict__ bi,
    const float* __restrict__ bf, const float* __restrict__ bo)
{
    extern __shared__ __nv_bfloat16 smb[];
    const uint32_t sb0 = smem_u32(smb);
    const int tid = threadIdx.x;
    const int wid = tid >> 5, lane = tid & 31;
    const int g = lane >> 2, t = lane & 3;
    const int wm = wid >> 2, wn = wid & 3;
    const int bx = blockIdx.x, by = blockIdx.y;
    const int n0 = bx * 128, m0 = by * 128;

    auto stage = [&](int c, int buf) {
        const uint32_t base = sb0 + (uint32_t)buf * (IG_BUF * 2);
        const uint4* srcA_h = (const uint4*)g_xh + (size_t)m0 * 64 + c * 8;
        const uint4* srcA_l = (const uint4*)g_xl + (size_t)m0 * 64 + c * 8;
        const uint4* srcB_h = (const uint4*)g_Wh + (size_t)n0 * 64 + c * 8;
        const uint4* srcB_l = (const uint4*)g_Wl + (size_t)n0 * 64 + c * 8;
        const uint4* srcs[4] = { srcA_h, srcA_l, srcB_h, srcB_l };
#pragma unroll
        for (int a = 0; a < 4; a++) {
#pragma unroll
            for (int i = 0; i < 4; i++) {
                const int idx = i * 256 + tid;
                const int r = idx >> 3, u = idx & 7;
                cpa16(base + (uint32_t)(a * (IG_ARR * 2) + r * (IG_PITCH * 2) + u * 16),
                      srcs[a] + (size_t)r * 64 + u);
            }
        }
        cpa_commit();
    };

    float acc[4][4][4];
#pragma unroll
    for (int mi = 0; mi < 4; mi++)
#pragma unroll
        for (int ni = 0; ni < 4; ni++)
#pragma unroll
            for (int r = 0; r < 4; r++) acc[mi][ni][r] = 0.0f;

    stage(0, 0);

    for (int c = 0; c < 8; c++) {
        cpa_wait0();
        __syncthreads();
        if (c + 1 < 8) stage(c + 1, (c + 1) & 1);

        const __nv_bfloat16* Ah = smb + (size_t)(c & 1) * IG_BUF;
        const __nv_bfloat16* Al = Ah + IG_ARR;
        const __nv_bfloat16* Bh = Ah + 2 * IG_ARR;
        const __nv_bfloat16* Bl = Ah + 3 * IG_ARR;

#pragma unroll
        for (int ks = 0; ks < 4; ks++) {
            const int k0 = ks * 16;
            uint32_t ah[4][4], al[4][4], bh[4][2], bl[4][2];
#pragma unroll
            for (int mi = 0; mi < 4; mi++) {
                const int r0 = wm * 64 + mi * 16 + g;
                const int cA = k0 + 2 * t;
                ah[mi][0] = *(const uint32_t*)(Ah + r0 * IG_PITCH + cA);
                ah[mi][1] = *(const uint32_t*)(Ah + (r0 + 8) * IG_PITCH + cA);
                ah[mi][2] = *(const uint32_t*)(Ah + r0 * IG_PITCH + cA + 8);
                ah[mi][3] = *(const uint32_t*)(Ah + (r0 + 8) * IG_PITCH + cA + 8);
                al[mi][0] = *(const uint32_t*)(Al + r0 * IG_PITCH + cA);
                al[mi][1] = *(const uint32_t*)(Al + (r0 + 8) * IG_PITCH + cA);
                al[mi][2] = *(const uint32_t*)(Al + r0 * IG_PITCH + cA + 8);
                al[mi][3] = *(const uint32_t*)(Al + (r0 + 8) * IG_PITCH + cA + 8);
            }
#pragma unroll
            for (int ni = 0; ni < 4; ni++) {
                const int rB = wn * 32 + ni * 8 + g;
                const int cB = k0 + 2 * t;
                bh[ni][0] = *(const uint32_t*)(Bh + rB * IG_PITCH + cB);
                bh[ni][1] = *(const uint32_t*)(Bh + rB * IG_PITCH + cB + 8);
                bl[ni][0] = *(const uint32_t*)(Bl + rB * IG_PITCH + cB);
                bl[ni][1] = *(const uint32_t*)(Bl + rB * IG_PITCH + cB + 8);
            }
#pragma unroll
            for (int mi = 0; mi < 4; mi++)
#pragma unroll
                for (int ni = 0; ni < 4; ni++) {
                    mma_bf16(acc[mi][ni], ah[mi], bh[ni]);
                    mma_bf16(acc[mi][ni], ah[mi], bl[ni]);
                    mma_bf16(acc[mi][ni], al[mi], bh[ni]);
                }
        }
        __syncthreads();
    }

    const int gate = bx >> 2;
    const float* bias = (gate == 0) ? bz : (gate == 1) ? bi : (gate == 2) ? bf : bo;
    const int nlb = (bx & 3) * 128;
#pragma unroll
    for (int mi = 0; mi < 4; mi++) {
        const int row0 = m0 + wm * 64 + mi * 16 + g;
        const int row1 = row0 + 8;
        const int s0 = row0 >> 5, b0 = row0 & 31;
        const int s1 = row1 >> 5, b1 = row1 & 31;
#pragma unroll
        for (int ni = 0; ni < 4; ni++) {
            const int nl = wn * 32 + ni * 8 + 2 * t;
            const int n = n0 + nl;
            const float bv0 = bias[nlb + nl], bv1 = bias[nlb + nl + 1];
            g_G[((size_t)s0 * 2048 + n) * BB + b0]     = acc[mi][ni][0] + bv0;
            g_G[((size_t)s0 * 2048 + n + 1) * BB + b0] = acc[mi][ni][1] + bv1;
            g_G[((size_t)s1 * 2048 + n) * BB + b1]     = acc[mi][ni][2] + bv0;
            g_G[((size_t)s1 * 2048 + n + 1) * BB + b1] = acc[mi][ni][3] + bv1;
        }
    }
}

// ---------------------------------------------------------------------------
// Tensor-core persistent recurrence. 128 blocks x 256 threads, 1 block/SM.
// Block = (n-group j = bid>>1 -> hcols jc=8j, b-half b0g=(bid&1)*16).
// Per step: pre[32 n][16 b] = G + R·h via mma.sync bf16 hi/lo (3 passes),
// 8 warps k-split x64, cp.async h staging, smem reduce, gate math (tid<128).
// smem (bf16 elems): Rs hi 0, lo 16640; hs hi 33280, lo 41600; total 49920.
#define RS_H 0
#define RS_L 16640
#define HS_H 33280
#define HS_L 41600
#define RC_PITCH 520
#define RC_SMEM (49920 * 2 + (4608 + 128 + 32) * 4)   // 118,912 B
__global__ void __launch_bounds__(NT, 1) recurrence(
    const float* __restrict__ brz, const float* __restrict__ bri,
    const float* __restrict__ brf, const float* __restrict__ bro)
{
    extern __shared__ __nv_bfloat16 smb[];
    float* red = (float*)(smb + 49920);   // [8][32][18] partials
    float* csm = red + 4608;              // 128 cell states
    float* brs = csm + 128;               // 32 biases (p = g*8+c)
    const uint32_t sbb = smem_u32(smb);

    const int tid = threadIdx.x;
    const int bid = blockIdx.x;
    const int jc  = (bid >> 1) * 8;
    const int b0g = (bid & 1) * 16;
    const int w = tid >> 5, lane = tid & 31;

    __shared__ unsigned s_base;
    if (tid == 0) s_base = g_gen;     // consistent snapshot (see R1 notes)

    // Stage R (32 rows m=g*8+c -> global n=g*512+jc+c), hi+lo, pitch 520.
    for (int i = 0; i < 16; i++) {
        const int idx = i * 256 + tid;            // 4096 uint4 total
        const int part = idx >> 11, rest = idx & 2047;
        const int m = rest >> 6, u = rest & 63;
        const int n = (m >> 3) * 512 + jc + (m & 7);
        const uint4 v = *((const uint4*)(part ? g_Rl : g_Rh) + (size_t)n * 64 + u);
        *(uint4*)(smb + (part ? RS_L : RS_H) + m * RC_PITCH + u * 8) = v;
    }
    if (tid < 32) {
        const int g = tid >> 3, c = tid & 7;
        const float* bg = (g == 0) ? brz : (g == 1) ? bri : (g == 2) ? brf : bro;
        brs[tid] = bg[jc + c];
    }
    if (tid < 128) csm[tid] = 0.0f;
    __syncthreads();
    const unsigned base = s_base;

    // ldmatrix lane-address components (per-warp tile shapes as R9)
    const int arow = (lane & 15) * RC_PITCH;          // A rows (m within tile)
    const int akad = (lane >> 4) << 3;                // +8 k for tiles 2,3
    const int brow = (((lane >> 4) & 1) * 8 + (lane & 7)) * RC_PITCH;  // B rows
    const int bkad = ((lane >> 3) & 1) * 8;           // +8 k for odd tiles
    // cell roles (threads 0..127)
    const int c_ = (tid >> 4) & 7;    // hcol 0..7
    const int b_ = tid & 15;          // batch 0..15
    const int grp = lane >> 2, qp = lane & 3;

    // G prefetch for s = 0 (threads 0..127)
    float gv0 = 0.f, gv1 = 0.f, gv2 = 0.f, gv3 = 0.f;
    if (tid < 128) {
        gv0 = g_G[(0 * 512 + jc + c_) * BB + b0g + b_];
        gv1 = g_G[(1 * 512 + jc + c_) * BB + b0g + b_];
        gv2 = g_G[(2 * 512 + jc + c_) * BB + b0g + b_];
        gv3 = g_G[(3 * 512 + jc + c_) * BB + b0g + b_];
    }

    float histv = 0.0f;
    int   hist_idx = -1;

    for (int s = 0; s < SS; ++s) {
        // Stage h (bf16 hi/lo, 16 b-rows x 512 k, pitch 520) via cp.async.
        if (s == 0) {
            const uint4 z4 = make_uint4(0, 0, 0, 0);
#pragma unroll
            for (int i = 0; i < 8; i++) {
                const int idx = i * 256 + tid;        // 2048 uint4
                const int part = idx >> 10, rest = idx & 1023;
                const int r = rest >> 6, u = rest & 63;
                *(uint4*)(smb + (part ? HS_L : HS_H) + r * RC_PITCH + u * 8) = z4;
            }
        } else {
            const int pb = (s - 1) & 1;
            const uint4* hsrc = (const uint4*)g_hbf;
#pragma unroll
            for (int i = 0; i < 8; i++) {
                const int idx = i * 256 + tid;
                const int part = idx >> 10, rest = idx & 1023;
                const int r = rest >> 6, u = rest & 63;
                cpa16(sbb + 2 * (uint32_t)((part ? HS_L : HS_H) + r * RC_PITCH + u * 8),
                      hsrc + ((size_t)((pb * 2 + part) * 32 + b0g + r)) * 64 + u);
            }
            cpa_commit();
            cpa_wait0();
        }
        __syncthreads();

        // MMA: warp w covers k in [w*64, w*64+64), 4 k-steps of 16.
        float acc[2][2][4];
#pragma unroll
        for (int mi = 0; mi < 2; mi++)
#pragma unroll
            for (int ni = 0; ni < 2; ni++)
#pragma unroll
                for (int r = 0; r < 4; r++) acc[mi][ni][r] = 0.0f;

#pragma unroll
        for (int ks = 0; ks < 4; ks++) {
            const int kb = w * 64 + ks * 16;
            uint32_t Ah0[4], Ah1[4], Al0[4], Al1[4], Bh[4], Bl[4];
            ldsm4(Ah0, sbb + 2 * (RS_H + arow + kb + akad));
            ldsm4(Ah1, sbb + 2 * (RS_H + 16 * RC_PITCH + arow + kb + akad));
            ldsm4(Al0, sbb + 2 * (RS_L + arow + kb + akad));
            ldsm4(Al1, sbb + 2 * (RS_L + 16 * RC_PITCH + arow + kb + akad));
            ldsm4(Bh,  sbb + 2 * (HS_H + brow + kb + bkad));
            ldsm4(Bl,  sbb + 2 * (HS_L + brow + kb + bkad));
            mma_bf16(acc[0][0], Ah0, Bh);     mma_bf16(acc[0][1], Ah0, Bh + 2);
            mma_bf16(acc[1][0], Ah1, Bh);     mma_bf16(acc[1][1], Ah1, Bh + 2);
            mma_bf16(acc[0][0], Ah0, Bl);     mma_bf16(acc[0][1], Ah0, Bl + 2);
            mma_bf16(acc[1][0], Ah1, Bl);     mma_bf16(acc[1][1], Ah1, Bl + 2);
            mma_bf16(acc[0][0], Al0, Bh);     mma_bf16(acc[0][1], Al0, Bh + 2);
            mma_bf16(acc[1][0], Al1, Bh);     mma_bf16(acc[1][1], Al1, Bh + 2);
        }

        // Partials -> red[w][n=0..31][b=0..15] pitch 18
#pragma unroll
        for (int mi = 0; mi < 2; mi++)
#pragma unroll
            for (int ni = 0; ni < 2; ni++) {
                const int row = mi * 16 + grp;
                const int col = ni * 8 + qp * 2;
                *(float2*)&red[(w * 32 + row) * 18 + col] =
                    make_float2(acc[mi][ni][0], acc[mi][ni][1]);
                *(float2*)&red[(w * 32 + row + 8) * 18 + col] =
                    make_float2(acc[mi][ni][2], acc[mi][ni][3]);
            }
        __syncthreads();

        // Gate phase (threads 0..127): cell (hcol c_, batch b_).
        if (tid < 128) {
            float pz = gv0 + brs[0 + c_];
            float pi_ = gv1 + brs[8 + c_];
            float pf = gv2 + brs[16 + c_];
            float po = gv3 + brs[24 + c_];
#pragma unroll
            for (int q = 0; q < 8; q++) {
                pz  += red[(q * 32 + 0 + c_) * 18 + b_];
                pi_ += red[(q * 32 + 8 + c_) * 18 + b_];
                pf  += red[(q * 32 + 16 + c_) * 18 + b_];
                po  += red[(q * 32 + 24 + c_) * 18 + b_];
            }
            const float z  = tanhf(pz);
            const float iv = sigf(pi_);
            const float f  = sigf(pf);
            const float o  = sigf(po);
            const float cc = fmaf(f, csm[tid], z * iv);
            csm[tid] = cc;
            const float h = o * tanhf(cc);
            // Emit h as bf16 hi/lo to [buf][part][b][k]
            const __nv_bfloat16 hh = __float2bfloat16_rn(h);
            const __nv_bfloat16 hl = __float2bfloat16_rn(h - __bfloat162float(hh));
            g_hbf[s & 1][0][b0g + b_][jc + c_] = hh;
            g_hbf[s & 1][1][b0g + b_][jc + c_] = hl;
            histv = h;
            hist_idx = (s >= SS / 2)
                     ? (int)(((size_t)(s - SS / 2) * BB + b0g + b_) * HH + jc + c_)
                     : -1;
        }

        // Prefetch next step's G, grid barrier, then deferred Hist store.
        if (s < SS - 1) {
            float t0 = 0.f, t1 = 0.f, t2 = 0.f, t3 = 0.f;
            if (tid < 128) {
                const float* Gn = g_G + (size_t)(s + 1) * (2048 * BB);
                t0 = Gn[(0 * 512 + jc + c_) * BB + b0g + b_];
                t1 = Gn[(1 * 512 + jc + c_) * BB + b0g + b_];
                t2 = Gn[(2 * 512 + jc + c_) * BB + b0g + b_];
                t3 = Gn[(3 * 512 + jc + c_) * BB + b0g + b_];
            }
            __threadfence();
            __syncthreads();
            if (tid == 0) {
                const unsigned tgt = base + (unsigned)s + 1u;
                if (atomicAdd(&g_cnt, 1u) == NB - 1u) {
                    atomicExch(&g_cnt, 0u);
                    __threadfence();
                    g_gen = tgt;
                } else {
                    while ((int)(g_gen - tgt) < 0) __nanosleep(32);
                    __threadfence();
                }
            }
            __syncthreads();
            if (hist_idx >= 0) g_Hist[hist_idx] = histv;
            gv0 = t0; gv1 = t1; gv2 = t2; gv3 = t3;
        } else {
            if (hist_idx >= 0) g_Hist[hist_idx] = histv;
        }
    }
    // Launch-exit state: g_cnt == 0, g_gen == base + SS - 1  (replay-safe).
}

// ---------------------------------------------------------------------------
// Output GEMM: out[b][s'][o] = Hist[s'][b][:] . Wl[o][:] + bl[o]  (fp32)
__global__ void __launch_bounds__(256, 2) output_gemm(
    const float* __restrict__ Wl, const float* __restrict__ bl,
    float* __restrict__ out)
{
    constexpr int BM = 128, BN = 128, BK = 8;
    __shared__ float As[BK][BM + 4];
    __shared__ float Bs[BK][BN + 4];

    const int bx = blockIdx.x;
    const int by = blockIdx.y;
    const int m0 = by * BM;
    const int n0g = bx * BN;

    const int tid  = threadIdx.x;
    const int arow = tid >> 1, acol = (tid & 1) * 4;
    const int brow = tid >> 1, bcol = (tid & 1) * 4;
    const int tx = tid & 15, ty = tid >> 4;

    const float* apk = g_Hist + (size_t)(m0 + arow) * HH + acol;
    const float* bpk = Wl + (size_t)(n0g + brow) * HH + bcol;

    unsigned long long acc2[8][4];
#pragma unroll
    for (int i = 0; i < 8; i++)
#pragma unroll
        for (int j = 0; j < 4; j++) acc2[i][j] = 0ULL;

    float4 av = *(const float4*)(apk);
    float4 bv = *(const float4*)(bpk);

    for (int k0 = 0; k0 < HH; k0 += BK) {
        As[acol + 0][arow] = av.x; As[acol + 1][arow] = av.y;
        As[acol + 2][arow] = av.z; As[acol + 3][arow] = av.w;
        Bs[bcol + 0][brow] = bv.x; Bs[bcol + 1][brow] = bv.y;
        Bs[bcol + 2][brow] = bv.z; Bs[bcol + 3][brow] = bv.w;
        __syncthreads();
        if (k0 + BK < HH) {
            av = *(const float4*)(apk + k0 + BK);
            bv = *(const float4*)(bpk + k0 + BK);
        }
#pragma unroll
        for (int k = 0; k < BK; k++) {
            float ra[8];
            *(float4*)(ra)     = *(const float4*)(&As[k][4 * ty]);
            *(float4*)(ra + 4) = *(const float4*)(&As[k][64 + 4 * ty]);
            const ulonglong2 b01 = *(const ulonglong2*)(&Bs[k][4 * tx]);
            const ulonglong2 b23 = *(const ulonglong2*)(&Bs[k][64 + 4 * tx]);
#pragma unroll
            for (int i = 0; i < 8; i++) {
                const unsigned long long a2 = splat2(ra[i]);
                ffma2(acc2[i][0], a2, b01.x);
                ffma2(acc2[i][1], a2, b01.y);
                ffma2(acc2[i][2], a2, b23.x);
                ffma2(acc2[i][3], a2, b23.y);
            }
        }
        __syncthreads();
    }

    float acc[8][8];
#pragma unroll
    for (int i = 0; i < 8; i++)
#pragma unroll
        for (int jp = 0; jp < 4; jp++) {
            float2 f = unpack2(acc2[i][jp]);
            acc[i][2 * jp] = f.x; acc[i][2 * jp + 1] = f.y;
        }

#pragma unroll
    for (int i = 0; i < 8; i++) {
        const int m = m0 + (i >> 2) * 64 + 4 * ty + (i & 3);
        const int sp = m >> 5, bB = m & 31;
#pragma unroll
        for (int jh = 0; jh < 2; jh++) {
            const int n = n0g + jh * 64 + 4 * tx;
            float4 v = make_float4(acc[i][jh * 4 + 0] + bl[n + 0],
                                   acc[i][jh * 4 + 1] + bl[n + 1],
                                   acc[i][jh * 4 + 2] + bl[n + 2],
                                   acc[i][jh * 4 + 3] + bl[n + 3]);
            *(float4*)(out + ((size_t)bB * (SS / 2) + sp) * II + n) = v;
        }
    }
}

// ---------------------------------------------------------------------------
extern "C" void kernel_launch(void* const* d_in, const int* in_sizes, int n_in,
                              void* d_out, int out_size)
{
    const float* x   = (const float*)d_in[0];
    const float* Wz  = (const float*)d_in[1];  const float* bz  = (const float*)d_in[2];
    const float* Wi  = (const float*)d_in[3];  const float* bi  = (const float*)d_in[4];
    const float* Wf  = (const float*)d_in[5];  const float* bf  = (const float*)d_in[6];
    const float* Wo  = (const float*)d_in[7];  const float* bo  = (const float*)d_in[8];
    const float* Rz  = (const float*)d_in[9];  const float* brz = (const float*)d_in[10];
    const float* Ri  = (const float*)d_in[11]; const float* bri = (const float*)d_in[12];
    const float* Rf  = (const float*)d_in[13]; const float* brf = (const float*)d_in[14];
    const float* Ro  = (const float*)d_in[15]; const float* bro = (const float*)d_in[16];
    const float* Wl  = (const float*)d_in[17]; const float* bl  = (const float*)d_in[18];
    float* out = (float*)d_out;

    // 0) Convert x/W/R to bf16 hi/lo
    convert_prepass<<<592, 256>>>(x, Wz, Wi, Wf, Wo, Rz, Ri, Rf, Ro);

    // 1) Tensor-core (HMMA) input projections -> g_G
    cudaFuncSetAttribute(input_gemm_tc, cudaFuncAttributeMaxDynamicSharedMemorySize, IG_SMEM);
    input_gemm_tc<<<dim3(16, 256), 256, IG_SMEM>>>(bz, bi, bf, bo);

    // 2) Tensor-core persistent recurrence -> g_Hist
    cudaFuncSetAttribute(recurrence, cudaFuncAttributeMaxDynamicSharedMemorySize, RC_SMEM);
    recurrence<<<NB, NT, RC_SMEM>>>(brz, bri, brf, bro);

    // 3) Output projection -> d_out
    output_gemm<<<dim3(4, 128), 256>>>(Wl, bl, out);
}